// round 3
// baseline (speedup 1.0000x reference)
#include <cuda_runtime.h>
#include <math.h>

// Problem constants
#define NN 768
#define NH 4
#define ND 3
#define HDIM 64
#define HID 64
#define HCDIM 80          // h (64) + sq_norms_heads (16)
#define EIN_K 164         // 4 + 80 + 80
#define TJ 128            // j-tile
#define NTILES (NN / TJ)  // 6? no: 768/128 = 6
// NOTE: 768/128 = 6 tiles

// shared memory layout (in floats)
#define O_WE0   0                      // [164][64]
#define O_WE1   (O_WE0 + 164*64)       // [64][64]
#define O_WX0   (O_WE1 + 64*64)
#define O_WX1   (O_WX0 + 64*64)
#define O_WX2   (O_WX1 + 64*64)        // [64][4]
#define O_WINF  (O_WX2 + 64*4)         // [64]
#define O_BE0   (O_WINF + 64)
#define O_BE1   (O_BE0 + 64)
#define O_BX0   (O_BE1 + 64)
#define O_BX1   (O_BX0 + 64)
#define O_BX2   (O_BX1 + 64)           // [4]
#define O_BINF  (O_BX2 + 4)            // [1] (pad to 4)
#define O_A     (O_BINF + 4)           // ein [128][170] ; later m_ij [128][66] + px1out [128][66]
#define EIN_STR 170
#define Z_STR   66
#define O_B     (O_A + TJ*EIN_STR)     // z buffer [128][66]
#define O_XJ    (O_B + TJ*Z_STR)       // [128][12]
#define O_HCI   (O_XJ + TJ*12)         // [80]
#define O_ES    (O_HCI + 80)           // [128]
#define O_MIS   (O_ES + TJ)            // [64]
#define O_SP    (O_MIS + 64)           // [256][3]
#define O_XI    (O_SP + 256*3)         // [12]
#define SMEM_FLOATS (O_XI + 16)
#define SMEM_BYTES (SMEM_FLOATS * 4)

// scratch (no cudaMalloc allowed)
__device__ float g_hc[NN * HCDIM];
__device__ float g_mi[NN * HID];

__device__ __forceinline__ unsigned long long pack2(float x, float y) {
    unsigned long long r;
    asm("mov.b64 %0, {%1, %2};" : "=l"(r) : "f"(x), "f"(y));
    return r;
}
__device__ __forceinline__ void unpack2(unsigned long long v, float& lo, float& hi) {
    asm("mov.b64 {%0, %1}, %2;" : "=f"(lo), "=f"(hi) : "l"(v));
}
__device__ __forceinline__ void fma2(unsigned long long& d, unsigned long long a, unsigned long long b) {
    asm("fma.rn.f32x2 %0, %1, %2, %0;" : "+l"(d) : "l"(a), "l"(b));
}
__device__ __forceinline__ float sigmoidf_(float x) { return 1.0f / (1.0f + __expf(-x)); }
__device__ __forceinline__ float siluf_(float x) { return x / (1.0f + __expf(-x)); }

// 128x64 GEMM tile: OUT[j][o] = act(bias[o] + sum_k IN[j][k] * W[k][o])
// W in smem [K][64] row-major, IN in smem [128][IN_STRIDE], OUT [128][Z_STR].
// 256 threads: micro-tile 4j x 8o per thread, f32x2 packed accumulators.
template<int K, int IN_STRIDE, bool DO_SILU>
__device__ __forceinline__ void gemm_tile(const float* __restrict__ W,
                                          const float* __restrict__ bias,
                                          const float* __restrict__ IN,
                                          float* __restrict__ OUT,
                                          int tid) {
    const int to = tid & 7;        // 8 groups along o
    const int tj = tid >> 3;       // 32 groups along j
    const int ob = to * 8;
    const int jb = tj * 4;
    unsigned long long acc[4][4];
#pragma unroll
    for (int a = 0; a < 4; a++)
#pragma unroll
        for (int b = 0; b < 4; b++) acc[a][b] = 0ull;

    const float* in0 = IN + jb * IN_STRIDE;
#pragma unroll 4
    for (int k = 0; k < K; k++) {
        const ulonglong2* wr = reinterpret_cast<const ulonglong2*>(W + k * 64 + ob);
        ulonglong2 wa = wr[0];
        ulonglong2 wb = wr[1];
#pragma unroll
        for (int jj = 0; jj < 4; jj++) {
            float e = in0[jj * IN_STRIDE + k];
            unsigned long long ep = pack2(e, e);
            fma2(acc[jj][0], ep, wa.x);
            fma2(acc[jj][1], ep, wa.y);
            fma2(acc[jj][2], ep, wb.x);
            fma2(acc[jj][3], ep, wb.y);
        }
    }
#pragma unroll
    for (int jj = 0; jj < 4; jj++) {
        float* orow = OUT + (jb + jj) * Z_STR + ob;
#pragma unroll
        for (int p = 0; p < 4; p++) {
            float lo, hi;
            unpack2(acc[jj][p], lo, hi);
            lo += bias[ob + 2 * p];
            hi += bias[ob + 2 * p + 1];
            if (DO_SILU) { lo = siluf_(lo); hi = siluf_(hi); }
            float2 v = make_float2(lo, hi);
            *reinterpret_cast<float2*>(orow + 2 * p) = v;
        }
    }
}

// Kernel A: h_concat[m] = [h[m] (64), ||x[m,b]-x[m,a]||^2 for (a,b) in 4x4 (16)]
__global__ void hc_kernel(const float* __restrict__ x, const float* __restrict__ h) {
    int m = blockIdx.x;
    int t = threadIdx.x;
    if (t < 64) {
        g_hc[m * HCDIM + t] = h[m * 64 + t];
    } else if (t < 80) {
        int p = t - 64;
        int a = p >> 2, b = p & 3;
        const float* xr = x + m * 12;
        float dx = xr[b * 3 + 0] - xr[a * 3 + 0];
        float dy = xr[b * 3 + 1] - xr[a * 3 + 1];
        float dz = xr[b * 3 + 2] - xr[a * 3 + 2];
        g_hc[m * HCDIM + t] = dx * dx + dy * dy + dz * dz;
    }
}

// Kernel B: per-node-i fused pair loop. Writes x_new rows into out[0:9216) and g_mi.
__global__ void __launch_bounds__(256, 1)
egcl_main(const float* __restrict__ x,
          const float* __restrict__ we0, const float* __restrict__ be0,
          const float* __restrict__ we1, const float* __restrict__ be1,
          const float* __restrict__ winf, const float* __restrict__ binf,
          const float* __restrict__ wx0, const float* __restrict__ bx0,
          const float* __restrict__ wx1, const float* __restrict__ bx1,
          const float* __restrict__ wx2, const float* __restrict__ bx2,
          float* __restrict__ out) {
    extern __shared__ float sm[];
    const int i = blockIdx.x;
    const int tid = threadIdx.x;

    // load weights + biases into smem
    for (int t = tid; t < 164 * 64; t += 256) sm[O_WE0 + t] = we0[t];
    for (int t = tid; t < 64 * 64; t += 256) {
        sm[O_WE1 + t] = we1[t];
        sm[O_WX0 + t] = wx0[t];
        sm[O_WX1 + t] = wx1[t];
    }
    for (int t = tid; t < 64 * 4; t += 256) sm[O_WX2 + t] = wx2[t];
    if (tid < 64) {
        sm[O_WINF + tid] = winf[tid];
        sm[O_BE0 + tid] = be0[tid];
        sm[O_BE1 + tid] = be1[tid];
        sm[O_BX0 + tid] = bx0[tid];
        sm[O_BX1 + tid] = bx1[tid];
    }
    if (tid < 4) sm[O_BX2 + tid] = bx2[tid];
    if (tid == 0) sm[O_BINF] = binf[0];
    if (tid < 80) sm[O_HCI + tid] = g_hc[i * HCDIM + tid];
    if (tid < 12) sm[O_XI + tid] = x[i * 12 + tid];
    if (tid < 64) sm[O_MIS + tid] = 0.0f;
    __syncthreads();

    float acc3_0 = 0.f, acc3_1 = 0.f, acc3_2 = 0.f;  // per-thread shift partial (head = tid&3)
    const int my_h = tid & 3;
    const int my_jg = tid >> 2;

    for (int tile = 0; tile < NN / TJ; tile++) {
        const int jt = tile * TJ;
        // load x tile
        for (int t = tid; t < TJ * 12; t += 256) sm[O_XJ + t] = x[jt * 12 + t];
        __syncthreads();

        // build ein [128][170]: [sqn(4) | hc_j(80) | hc_i(80)]
        float* ein = sm + O_A;
        for (int t = tid; t < TJ * HCDIM; t += 256) {
            int j = t / HCDIM, k2 = t - j * HCDIM;
            float hcv = g_hc[(jt + j) * HCDIM + k2];
            ein[j * EIN_STR + 4 + k2] = hcv;
            ein[j * EIN_STR + 84 + k2] = sm[O_HCI + k2];
        }
        for (int t = tid; t < TJ * NH; t += 256) {
            int j = t >> 2, hh = t & 3;
            const float* xa = sm + O_XJ + j * 12 + hh * 3;
            const float* xb = sm + O_XI + hh * 3;
            float dx = xa[0] - xb[0], dy = xa[1] - xb[1], dz = xa[2] - xb[2];
            ein[j * EIN_STR + hh] = dx * dx + dy * dy + dz * dz;
        }
        __syncthreads();

        // phi_e layer 0: ein -> B (silu)
        gemm_tile<EIN_K, EIN_STR, true>(sm + O_WE0, sm + O_BE0, ein, sm + O_B, tid);
        __syncthreads();
        // phi_e layer 1: B -> m_ij (A, stride 66) (silu)
        gemm_tile<64, Z_STR, true>(sm + O_WE1, sm + O_BE1, sm + O_B, sm + O_A, tid);
        __syncthreads();

        // phi_inf -> e (masked at diagonal)
        if (tid < TJ) {
            int j = tid;
            const float* mr = sm + O_A + j * Z_STR;
            float d = sm[O_BINF];
            float s = 0.f;
#pragma unroll 8
            for (int k = 0; k < 64; k++) s += mr[k] * sm[O_WINF + k];
            d += s;
            float e = sigmoidf_(d);
            if (jt + j == i) e = 0.f;
            sm[O_ES + j] = e;
        }
        __syncthreads();

        // m_i accumulation (64 threads, one output dim each)
        if (tid < 64) {
            float a = 0.f;
            for (int j = 0; j < TJ; j++) a += sm[O_ES + j] * sm[O_A + j * Z_STR + tid];
            sm[O_MIS + tid] += a;
        }
        // phi_x layer 0: m_ij(A) -> B (silu). No race with m_i accum (both read A).
        gemm_tile<64, Z_STR, true>(sm + O_WX0, sm + O_BX0, sm + O_A, sm + O_B, tid);
        __syncthreads();
        // phi_x layer 1: B -> A2 (silu)
        gemm_tile<64, Z_STR, true>(sm + O_WX1, sm + O_BX1, sm + O_B, sm + O_A + TJ * Z_STR, tid);
        __syncthreads();

        // phi_x layer 2 (64->4) + equivariant shift accumulation
        {
#pragma unroll
            for (int q = 0; q < 2; q++) {
                int j = my_jg * 2 + q;
                const float* r = sm + O_A + TJ * Z_STR + j * Z_STR;
                float d = sm[O_BX2 + my_h];
#pragma unroll 8
                for (int k = 0; k < 64; k++) d += r[k] * sm[O_WX2 + k * 4 + my_h];
                const float* xa = sm + O_XJ + j * 12 + my_h * 3;
                const float* xb = sm + O_XI + my_h * 3;
                float dx = xa[0] - xb[0], dy = xa[1] - xb[1], dz = xa[2] - xb[2];
                float sq = dx * dx + dy * dy + dz * dz;
                float nrm = sqrtf(sq == 0.f ? 1.f : sq) + 1.f;
                float c = d / nrm;
                if (jt + j == i) c = 0.f;
                acc3_0 += c * dx;
                acc3_1 += c * dy;
                acc3_2 += c * dz;
            }
        }
        __syncthreads();  // before next tile overwrites xj / ein
    }

    // finalize m_i
    if (tid < 64) g_mi[i * 64 + tid] = sm[O_MIS + tid] * (1.0f / sqrtf(767.0f));

    // reduce shift partials -> x_new
    sm[O_SP + tid * 3 + 0] = acc3_0;
    sm[O_SP + tid * 3 + 1] = acc3_1;
    sm[O_SP + tid * 3 + 2] = acc3_2;
    __syncthreads();
    if (tid < 12) {
        int hh = tid / 3, d = tid - hh * 3;
        float s = 0.f;
        for (int jg = 0; jg < 64; jg++) s += sm[O_SP + (jg * 4 + hh) * 3 + d];
        out[i * 12 + hh * 3 + d] = sm[O_XI + hh * 3 + d] + s * (1.0f / 767.0f);
    }
}

// Kernel C: phi_h per node: h_new = h + MLP2([m_i, h]) @ w2 + b2
__global__ void phi_h_kernel(const float* __restrict__ h,
                             const float* __restrict__ w0, const float* __restrict__ b0,
                             const float* __restrict__ w1, const float* __restrict__ b1,
                             const float* __restrict__ w2, const float* __restrict__ b2,
                             float* __restrict__ out) {
    __shared__ float in1[128], t0[64], t1[64];
    const int i = blockIdx.x;
    const int o = threadIdx.x;  // 64 threads
    in1[o] = g_mi[i * 64 + o];
    in1[64 + o] = h[i * 64 + o];
    __syncthreads();
    float a = b0[o];
#pragma unroll 4
    for (int k = 0; k < 128; k++) a += in1[k] * w0[k * 64 + o];
    t0[o] = siluf_(a);
    __syncthreads();
    a = b1[o];
#pragma unroll 4
    for (int k = 0; k < 64; k++) a += t0[k] * w1[k * 64 + o];
    t1[o] = siluf_(a);
    __syncthreads();
    a = b2[o];
#pragma unroll 4
    for (int k = 0; k < 64; k++) a += t1[k] * w2[k * 64 + o];
    out[NN * 12 + i * 64 + o] = h[i * 64 + o] + a;
}

extern "C" void kernel_launch(void* const* d_in, const int* in_sizes, int n_in,
                              void* d_out, int out_size) {
    const float* x    = (const float*)d_in[0];
    const float* h    = (const float*)d_in[1];
    const float* we0  = (const float*)d_in[2];
    const float* be0  = (const float*)d_in[3];
    const float* we1  = (const float*)d_in[4];
    const float* be1  = (const float*)d_in[5];
    const float* winf = (const float*)d_in[6];
    const float* binf = (const float*)d_in[7];
    const float* wx0  = (const float*)d_in[8];
    const float* bx0  = (const float*)d_in[9];
    const float* wx1  = (const float*)d_in[10];
    const float* bx1  = (const float*)d_in[11];
    const float* wx2  = (const float*)d_in[12];
    const float* bx2  = (const float*)d_in[13];
    const float* wh0  = (const float*)d_in[14];
    const float* bh0  = (const float*)d_in[15];
    const float* wh1  = (const float*)d_in[16];
    const float* bh1  = (const float*)d_in[17];
    const float* wh2  = (const float*)d_in[18];
    const float* bh2  = (const float*)d_in[19];
    float* out = (float*)d_out;

    cudaFuncSetAttribute(egcl_main, cudaFuncAttributeMaxDynamicSharedMemorySize, SMEM_BYTES);

    hc_kernel<<<NN, 96>>>(x, h);
    egcl_main<<<NN, 256, SMEM_BYTES>>>(x, we0, be0, we1, be1, winf, binf,
                                       wx0, bx0, wx1, bx1, wx2, bx2, out);
    phi_h_kernel<<<NN, 64>>>(h, wh0, bh0, wh1, bh1, wh2, bh2, out);
}

// round 7
// speedup vs baseline: 1.9370x; 1.9370x over previous
#include <cuda_runtime.h>
#include <math.h>

// ---------------- problem constants ----------------
#define NN 768
#define NH 4
#define HDIM 64
#define HID 64
#define TJ 64             // j-tile
#define NTILES (NN / TJ)  // 12
#define ZST 68            // activation row stride (floats)

// ---------------- smem layout (floats) ----------------
#define O_W1    0                       // we1 permuted [64][64]
#define O_WX0   (O_W1 + 4096)
#define O_WX1   (O_WX0 + 4096)
#define O_WX2   (O_WX1 + 4096)          // [64][4]
#define O_WE0H  (O_WX2 + 256)           // we0 rows 0..3 [4][64]
#define O_WINF  (O_WE0H + 256)          // [64]
#define O_BE1   (O_WINF + 64)
#define O_BX0   (O_BE1 + 64)
#define O_BX1   (O_BX0 + 64)
#define O_BX2   (O_BX1 + 64)            // [4]
#define O_BINF  (O_BX2 + 4)             // [4]
#define O_C     (O_BINF + 4)            // [64]
#define O_XI    (O_C + 64)              // [16]
#define O_B0    (O_XI + 16)             // [64][68]
#define O_B1    (O_B0 + TJ*ZST)         // [64][68]
#define O_XJ    (O_B1 + TJ*ZST)         // [64][12]
#define O_SQN   (O_XJ + TJ*12)          // [64][4]
#define O_EPRE  (O_SQN + 256)           // [64]
#define O_E     (O_EPRE + 64)           // [64]
#define O_MP    (O_E + 64)              // [4][64]
#define O_M     (O_MP + 256)            // [64]
#define O_SP    (O_M + 64)              // [256][3]
#define SMEM_FLOATS (O_SP + 768)
#define SMEM_BYTES (SMEM_FLOATS * 4)

// scratch (no cudaMalloc allowed)
__device__ float g_G[NN * 64];   // hc_j @ We0[4:84] + be0
__device__ float g_C[NN * 64];   // hc_i @ We0[84:164]
__device__ float g_mi[NN * HID];

__device__ __forceinline__ unsigned long long pack2(float x, float y) {
    unsigned long long r;
    asm("mov.b64 %0, {%1, %2};" : "=l"(r) : "f"(x), "f"(y));
    return r;
}
__device__ __forceinline__ void unpack2(unsigned long long v, float& lo, float& hi) {
    asm("mov.b64 {%0, %1}, %2;" : "=f"(lo), "=f"(hi) : "l"(v));
}
__device__ __forceinline__ void fma2(unsigned long long& d, unsigned long long a, unsigned long long b) {
    asm("fma.rn.f32x2 %0, %1, %2, %0;" : "+l"(d) : "l"(a), "l"(b));
}
__device__ __forceinline__ float sigmoidf_(float x) { return 1.0f / (1.0f + __expf(-x)); }
__device__ __forceinline__ float siluf_(float x) { return x / (1.0f + __expf(-x)); }

// weight permutation: o -> pos so both LDS.128 halves are bank-conflict-free
__device__ __forceinline__ int wperm(int o) {
    return ((o >> 2) & 1) * 32 + (o >> 3) * 4 + (o & 3);
}

// ---------------- prep: G[m]=hc_m@We0[4:84]+be0, C[m]=hc_m@We0[84:164] ----------------
__global__ void prep_kernel(const float* __restrict__ x, const float* __restrict__ h,
                            const float* __restrict__ we0, const float* __restrict__ be0) {
    __shared__ float hc[80];
    const int m = blockIdx.x;
    const int t = threadIdx.x;  // 128
    if (t < 64) {
        hc[t] = h[m * 64 + t];
    } else if (t < 80) {
        int p = t - 64;
        int a = p >> 2, b = p & 3;
        const float* xr = x + m * 12;
        float dx = xr[b * 3 + 0] - xr[a * 3 + 0];
        float dy = xr[b * 3 + 1] - xr[a * 3 + 1];
        float dz = xr[b * 3 + 2] - xr[a * 3 + 2];
        hc[t] = dx * dx + dy * dy + dz * dz;
    }
    __syncthreads();
    const int o = t & 63;
    const float* W = we0 + ((t < 64) ? 4 * 64 : 84 * 64);
    float a = (t < 64) ? be0[o] : 0.0f;
#pragma unroll 8
    for (int k = 0; k < 80; k++) a += hc[k] * W[k * 64 + o];
    if (t < 64) g_G[m * 64 + o] = a;
    else        g_C[m * 64 + o] = a;
}

// 64x64 GEMM over a 64-j tile: OUT[j][o] = silu(bias[o] + sum_k IN[j][k]*W[k][o])
// Wp permuted layout; IN/OUT row-major stride ZST. 256 threads: 2j x 8o per thread.
template<bool EPRE>
__device__ __forceinline__ void gemm64(const float* __restrict__ Wp,
                                       const float* __restrict__ bias,
                                       const float* __restrict__ IN,
                                       float* __restrict__ OUT,
                                       float* __restrict__ epre_buf,
                                       const float* __restrict__ winf,
                                       int tid) {
    const int to = tid & 7;
    const int tj = tid >> 3;
    const int ob = to * 8;
    const int j0 = tj * 2;
    unsigned long long acc0[4], acc1[4];
#pragma unroll
    for (int p = 0; p < 4; p++) { acc0[p] = 0ull; acc1[p] = 0ull; }

    const float4* r0 = reinterpret_cast<const float4*>(IN + j0 * ZST);
    const float4* r1 = reinterpret_cast<const float4*>(IN + (j0 + 1) * ZST);
#pragma unroll 4
    for (int k4 = 0; k4 < 16; k4++) {
        float4 a0 = r0[k4];
        float4 a1 = r1[k4];
        const float* wbase = Wp + k4 * 256 + to * 4;
#pragma unroll
        for (int kk = 0; kk < 4; kk++) {
            ulonglong2 wa = *reinterpret_cast<const ulonglong2*>(wbase + kk * 64);
            ulonglong2 wb = *reinterpret_cast<const ulonglong2*>(wbase + kk * 64 + 32);
            float e0 = (&a0.x)[kk];
            float e1 = (&a1.x)[kk];
            unsigned long long p0 = pack2(e0, e0);
            unsigned long long p1 = pack2(e1, e1);
            fma2(acc0[0], p0, wa.x); fma2(acc0[1], p0, wa.y);
            fma2(acc0[2], p0, wb.x); fma2(acc0[3], p0, wb.y);
            fma2(acc1[0], p1, wa.x); fma2(acc1[1], p1, wa.y);
            fma2(acc1[2], p1, wb.x); fma2(acc1[3], p1, wb.y);
        }
    }
    // epilogue: bias + silu + store (+ optional winf dot for phi_inf)
    float o0[8], o1[8];
#pragma unroll
    for (int p = 0; p < 4; p++) {
        float lo, hi;
        unpack2(acc0[p], lo, hi);
        o0[2 * p]     = siluf_(lo + bias[ob + 2 * p]);
        o0[2 * p + 1] = siluf_(hi + bias[ob + 2 * p + 1]);
        unpack2(acc1[p], lo, hi);
        o1[2 * p]     = siluf_(lo + bias[ob + 2 * p]);
        o1[2 * p + 1] = siluf_(hi + bias[ob + 2 * p + 1]);
    }
    float4* s0 = reinterpret_cast<float4*>(OUT + j0 * ZST + ob);
    float4* s1 = reinterpret_cast<float4*>(OUT + (j0 + 1) * ZST + ob);
    s0[0] = make_float4(o0[0], o0[1], o0[2], o0[3]);
    s0[1] = make_float4(o0[4], o0[5], o0[6], o0[7]);
    s1[0] = make_float4(o1[0], o1[1], o1[2], o1[3]);
    s1[1] = make_float4(o1[4], o1[5], o1[6], o1[7]);
    if (EPRE) {
        float d0 = 0.f, d1 = 0.f;
#pragma unroll
        for (int p = 0; p < 8; p++) {
            float w = winf[ob + p];
            d0 += o0[p] * w;
            d1 += o1[p] * w;
        }
#pragma unroll
        for (int s = 1; s < 8; s <<= 1) {
            d0 += __shfl_xor_sync(0xffffffffu, d0, s);
            d1 += __shfl_xor_sync(0xffffffffu, d1, s);
        }
        if (to == 0) { epre_buf[j0] = d0; epre_buf[j0 + 1] = d1; }
    }
}

// ---------------- main fused pair kernel ----------------
__global__ void __launch_bounds__(256, 2)
egcl_main(const float* __restrict__ x,
          const float* __restrict__ we0,
          const float* __restrict__ we1, const float* __restrict__ be1,
          const float* __restrict__ winf, const float* __restrict__ binf,
          const float* __restrict__ wx0, const float* __restrict__ bx0,
          const float* __restrict__ wx1, const float* __restrict__ bx1,
          const float* __restrict__ wx2, const float* __restrict__ bx2,
          float* __restrict__ out) {
    extern __shared__ float sm[];
    const int i = blockIdx.x;
    const int tid = threadIdx.x;

    // load + permute weights
    for (int t = tid; t < 4096; t += 256) {
        int k = t >> 6, o = t & 63;
        int pos = k * 64 + wperm(o);
        sm[O_W1 + pos]  = we1[t];
        sm[O_WX0 + pos] = wx0[t];
        sm[O_WX1 + pos] = wx1[t];
    }
    if (tid < 256) sm[O_WX2 + tid] = wx2[tid];
    if (tid < 256) sm[O_WE0H + tid] = we0[tid];   // first 4 rows of we0
    if (tid < 64) {
        sm[O_WINF + tid] = winf[tid];
        sm[O_BE1 + tid]  = be1[tid];
        sm[O_BX0 + tid]  = bx0[tid];
        sm[O_BX1 + tid]  = bx1[tid];
        sm[O_C + tid]    = g_C[i * 64 + tid];
        sm[O_M + tid]    = 0.0f;
    }
    if (tid < 4) sm[O_BX2 + tid] = bx2[tid];
    if (tid == 0) sm[O_BINF] = binf[0];
    if (tid < 12) sm[O_XI + tid] = x[i * 12 + tid];
    __syncthreads();

    const int to = tid & 7;
    const int tj = tid >> 3;
    const int ob = to * 8;
    const int j0 = tj * 2;
    const int jslot = tid >> 2;       // phi_x2 mapping
    const int my_h  = tid & 3;
    float acc3_0 = 0.f, acc3_1 = 0.f, acc3_2 = 0.f;

    for (int tile = 0; tile < NTILES; tile++) {
        const int jt = tile * TJ;

        // xj tile
        for (int t = tid; t < TJ * 12; t += 256) sm[O_XJ + t] = x[jt * 12 + t];
        __syncthreads();

        // sqn[j][h]
        {
            int j = tid >> 2, hh = tid & 3;
            const float* xa = sm + O_XJ + j * 12 + hh * 3;
            const float* xb = sm + O_XI + hh * 3;
            float dx = xa[0] - xb[0], dy = xa[1] - xb[1], dz = xa[2] - xb[2];
            sm[O_SQN + j * 4 + hh] = dx * dx + dy * dy + dz * dz;
        }
        __syncthreads();

        // phi_e layer 0 via decomposition: z0 = silu(G[j] + C[i] + sqn@We0[0:4])
        {
            float4 c0 = *reinterpret_cast<const float4*>(sm + O_C + ob);
            float4 c1 = *reinterpret_cast<const float4*>(sm + O_C + ob + 4);
#pragma unroll
            for (int jj = 0; jj < 2; jj++) {
                int j = j0 + jj;
                float4 gA = *reinterpret_cast<const float4*>(g_G + (jt + j) * 64 + ob);
                float4 gB = *reinterpret_cast<const float4*>(g_G + (jt + j) * 64 + ob + 4);
                float pre[8];
                pre[0] = gA.x + c0.x; pre[1] = gA.y + c0.y;
                pre[2] = gA.z + c0.z; pre[3] = gA.w + c0.w;
                pre[4] = gB.x + c1.x; pre[5] = gB.y + c1.y;
                pre[6] = gB.z + c1.z; pre[7] = gB.w + c1.w;
#pragma unroll
                for (int hh = 0; hh < 4; hh++) {
                    float s = sm[O_SQN + j * 4 + hh];
                    float4 wA = *reinterpret_cast<const float4*>(sm + O_WE0H + hh * 64 + ob);
                    float4 wB = *reinterpret_cast<const float4*>(sm + O_WE0H + hh * 64 + ob + 4);
                    pre[0] += s * wA.x; pre[1] += s * wA.y;
                    pre[2] += s * wA.z; pre[3] += s * wA.w;
                    pre[4] += s * wB.x; pre[5] += s * wB.y;
                    pre[6] += s * wB.z; pre[7] += s * wB.w;
                }
                float4* st = reinterpret_cast<float4*>(sm + O_B0 + j * ZST + ob);
                st[0] = make_float4(siluf_(pre[0]), siluf_(pre[1]), siluf_(pre[2]), siluf_(pre[3]));
                st[1] = make_float4(siluf_(pre[4]), siluf_(pre[5]), siluf_(pre[6]), siluf_(pre[7]));
            }
        }
        __syncthreads();

        // phi_e layer 1: B0 -> B1 (m_ij), with fused phi_inf dot -> epre
        gemm64<true>(sm + O_W1, sm + O_BE1, sm + O_B0, sm + O_B1,
                     sm + O_EPRE, sm + O_WINF, tid);
        __syncthreads();

        // e[j] = sigmoid(epre + binf), diag-masked
        if (tid < TJ) {
            float v = sigmoidf_(sm[O_EPRE + tid] + sm[O_BINF]);
            if (jt + tid == i) v = 0.0f;
            sm[O_E + tid] = v;
        }
        __syncthreads();

        // m_i partials (reads B1) + phi_x layer 0 (reads B1 -> B0)
        {
            int o = tid & 63, seg = tid >> 6;
            float p = 0.f;
#pragma unroll 4
            for (int jj = 0; jj < 16; jj++) {
                int j = seg * 16 + jj;
                p += sm[O_E + j] * sm[O_B1 + j * ZST + o];
            }
            sm[O_MP + seg * 64 + o] = p;
        }
        gemm64<false>(sm + O_WX0, sm + O_BX0, sm + O_B1, sm + O_B0,
                      nullptr, nullptr, tid);
        __syncthreads();

        // reduce m_i partials; phi_x layer 1: B0 -> B1
        if (tid < 64) {
            sm[O_M + tid] += sm[O_MP + tid] + sm[O_MP + 64 + tid]
                           + sm[O_MP + 128 + tid] + sm[O_MP + 192 + tid];
        }
        gemm64<false>(sm + O_WX1, sm + O_BX1, sm + O_B0, sm + O_B1,
                      nullptr, nullptr, tid);
        __syncthreads();

        // phi_x layer 2 (64->4) + equivariant shift accumulation
        {
            float d = sm[O_BX2 + my_h];
            const float* r = sm + O_B1 + jslot * ZST;
#pragma unroll 8
            for (int k = 0; k < 64; k++) d += r[k] * sm[O_WX2 + k * 4 + my_h];
            const float* xa = sm + O_XJ + jslot * 12 + my_h * 3;
            const float* xb = sm + O_XI + my_h * 3;
            float dx = xa[0] - xb[0], dy = xa[1] - xb[1], dz = xa[2] - xb[2];
            float sq = dx * dx + dy * dy + dz * dz;
            float nrm = sqrtf(sq == 0.f ? 1.f : sq) + 1.f;
            float c = d / nrm;
            if (jt + jslot == i) c = 0.f;
            acc3_0 += c * dx;
            acc3_1 += c * dy;
            acc3_2 += c * dz;
        }
        __syncthreads();  // before next tile overwrites xj/B0/B1
    }

    // finalize m_i
    if (tid < 64) g_mi[i * 64 + tid] = sm[O_M + tid] * (1.0f / sqrtf(767.0f));

    // reduce shift partials -> x_new
    sm[O_SP + tid * 3 + 0] = acc3_0;
    sm[O_SP + tid * 3 + 1] = acc3_1;
    sm[O_SP + tid * 3 + 2] = acc3_2;
    __syncthreads();
    if (tid < 12) {
        int hh = tid / 3, d = tid - hh * 3;
        float s = 0.f;
#pragma unroll 8
        for (int js = 0; js < 64; js++) s += sm[O_SP + (js * 4 + hh) * 3 + d];
        out[i * 12 + hh * 3 + d] = sm[O_XI + hh * 3 + d] + s * (1.0f / 767.0f);
    }
}

// ---------------- phi_h per node ----------------
__global__ void phi_h_kernel(const float* __restrict__ h,
                             const float* __restrict__ w0, const float* __restrict__ b0,
                             const float* __restrict__ w1, const float* __restrict__ b1,
                             const float* __restrict__ w2, const float* __restrict__ b2,
                             float* __restrict__ out) {
    __shared__ float in1[128], t0[64], t1[64];
    const int i = blockIdx.x;
    const int o = threadIdx.x;  // 64 threads
    in1[o] = g_mi[i * 64 + o];
    in1[64 + o] = h[i * 64 + o];
    __syncthreads();
    float a = b0[o];
#pragma unroll 4
    for (int k = 0; k < 128; k++) a += in1[k] * w0[k * 64 + o];
    t0[o] = siluf_(a);
    __syncthreads();
    a = b1[o];
#pragma unroll 4
    for (int k = 0; k < 64; k++) a += t0[k] * w1[k * 64 + o];
    t1[o] = siluf_(a);
    __syncthreads();
    a = b2[o];
#pragma unroll 4
    for (int k = 0; k < 64; k++) a += t1[k] * w2[k * 64 + o];
    out[NN * 12 + i * 64 + o] = h[i * 64 + o] + a;
}

extern "C" void kernel_launch(void* const* d_in, const int* in_sizes, int n_in,
                              void* d_out, int out_size) {
    const float* x    = (const float*)d_in[0];
    const float* h    = (const float*)d_in[1];
    const float* we0  = (const float*)d_in[2];
    const float* be0  = (const float*)d_in[3];
    const float* we1  = (const float*)d_in[4];
    const float* be1  = (const float*)d_in[5];
    const float* winf = (const float*)d_in[6];
    const float* binf = (const float*)d_in[7];
    const float* wx0  = (const float*)d_in[8];
    const float* bx0  = (const float*)d_in[9];
    const float* wx1  = (const float*)d_in[10];
    const float* bx1  = (const float*)d_in[11];
    const float* wx2  = (const float*)d_in[12];
    const float* bx2  = (const float*)d_in[13];
    const float* wh0  = (const float*)d_in[14];
    const float* bh0  = (const float*)d_in[15];
    const float* wh1  = (const float*)d_in[16];
    const float* bh1  = (const float*)d_in[17];
    const float* wh2  = (const float*)d_in[18];
    const float* bh2  = (const float*)d_in[19];
    float* out = (float*)d_out;

    cudaFuncSetAttribute(egcl_main, cudaFuncAttributeMaxDynamicSharedMemorySize, SMEM_BYTES);

    prep_kernel<<<NN, 128>>>(x, h, we0, be0);
    egcl_main<<<NN, 256, SMEM_BYTES>>>(x, we0, we1, be1, winf, binf,
                                       wx0, bx0, wx1, bx1, wx2, bx2, out);
    phi_h_kernel<<<NN, 64>>>(h, wh0, bh0, wh1, bh1, wh2, bh2, out);
}

// round 9
// speedup vs baseline: 1.9726x; 1.0184x over previous
#include <cuda_runtime.h>
#include <math.h>

// ---------------- problem constants ----------------
#define NN 768
#define TJ 64             // j-tile
#define NTILES (NN / TJ)  // 12
#define ZST 68            // activation row stride (floats)

// ---------------- smem layout (floats) ----------------
#define O_W1    0                       // we1 permuted [64][64]
#define O_WX0   (O_W1 + 4096)
#define O_WX1   (O_WX0 + 4096)
#define O_WX2T  (O_WX1 + 4096)          // wx2 transposed [4][64]
#define O_WE0H  (O_WX2T + 256)          // we0 rows 0..3 [4][64]
#define O_WINF  (O_WE0H + 256)          // [64]
#define O_BE1   (O_WINF + 64)
#define O_BX0   (O_BE1 + 64)
#define O_BX1   (O_BX0 + 64)
#define O_BX2   (O_BX1 + 64)            // [4]
#define O_C     (O_BX2 + 4)             // [64]
#define O_B0    (O_C + 64)              // [64][68]
#define O_B1    (O_B0 + TJ*ZST)         // [64][68]
#define O_E     (O_B1 + TJ*ZST)         // [64]
#define O_MP    (O_E + 64)              // [4][64]
#define O_M     (O_MP + 256)            // [64]
#define O_SP    (O_M + 64)              // [256][3]
#define SMEM_FLOATS (O_SP + 768)
#define SMEM_BYTES (SMEM_FLOATS * 4)

// scratch (no cudaMalloc allowed)
__device__ float g_G[NN * 64];   // hc_j @ We0[4:84] + be0
__device__ float g_C[NN * 64];   // hc_i @ We0[84:164]
__device__ float g_mi[NN * 64];

#define LOG2E 1.4426950408889634f

__device__ __forceinline__ unsigned long long pack2(float x, float y) {
    unsigned long long r;
    asm("mov.b64 %0, {%1, %2};" : "=l"(r) : "f"(x), "f"(y));
    return r;
}
__device__ __forceinline__ void unpack2(unsigned long long v, float& lo, float& hi) {
    asm("mov.b64 {%0, %1}, %2;" : "=f"(lo), "=f"(hi) : "l"(v));
}
__device__ __forceinline__ void fma2(unsigned long long& d, unsigned long long a, unsigned long long b) {
    asm("fma.rn.f32x2 %0, %1, %2, %0;" : "+l"(d) : "l"(a), "l"(b));
}
__device__ __forceinline__ float rcpf_(float x) {
    float r; asm("rcp.approx.ftz.f32 %0, %1;" : "=f"(r) : "f"(x)); return r;
}
__device__ __forceinline__ float ex2f_(float x) {
    float r; asm("ex2.approx.ftz.f32 %0, %1;" : "=f"(r) : "f"(x)); return r;
}
__device__ __forceinline__ float rsqf_(float x) {
    float r; asm("rsqrt.approx.ftz.f32 %0, %1;" : "=f"(r) : "f"(x)); return r;
}
__device__ __forceinline__ float sigmoidf_(float x) {
    return rcpf_(1.0f + ex2f_(-x * LOG2E));
}
__device__ __forceinline__ float siluf_(float x) {
    return x * rcpf_(1.0f + ex2f_(-x * LOG2E));
}

// weight permutation: o -> pos so both LDS.128 halves are bank-conflict-free
__device__ __forceinline__ int wperm(int o) {
    return ((o >> 2) & 1) * 32 + (o >> 3) * 4 + (o & 3);
}

// ---------------- prep: G[m]=hc_m@We0[4:84]+be0, C[m]=hc_m@We0[84:164] ----------------
__global__ void prep_kernel(const float* __restrict__ x, const float* __restrict__ h,
                            const float* __restrict__ we0, const float* __restrict__ be0) {
    __shared__ float hc[80];
    const int m = blockIdx.x;
    const int t = threadIdx.x;  // 128
    if (t < 64) {
        hc[t] = h[m * 64 + t];
    } else if (t < 80) {
        int p = t - 64;
        int a = p >> 2, b = p & 3;
        const float* xr = x + m * 12;
        float dx = xr[b * 3 + 0] - xr[a * 3 + 0];
        float dy = xr[b * 3 + 1] - xr[a * 3 + 1];
        float dz = xr[b * 3 + 2] - xr[a * 3 + 2];
        hc[t] = dx * dx + dy * dy + dz * dz;
    }
    __syncthreads();
    const int o = t & 63;
    const float* W = we0 + ((t < 64) ? 4 * 64 : 84 * 64);
    float a = (t < 64) ? be0[o] : 0.0f;
#pragma unroll 8
    for (int k = 0; k < 80; k++) a += hc[k] * W[k * 64 + o];
    if (t < 64) g_G[m * 64 + o] = a;
    else        g_C[m * 64 + o] = a;
}

// 64x64 GEMM over a 64-j tile: OUT[j][o] = silu(bias[o] + sum_k IN[j][k]*W[k][o])
// Wp permuted; IN/OUT stride ZST. 256 threads: 2j x 8o per thread.
// If EPRE: fuse phi_inf dot + sigmoid + diag-mask, write e[j] directly.
template<bool EPRE>
__device__ __forceinline__ void gemm64(const float* __restrict__ Wp,
                                       const float* __restrict__ bias,
                                       const float* __restrict__ IN,
                                       float* __restrict__ OUT,
                                       float* __restrict__ e_buf,
                                       const float* __restrict__ winf,
                                       float rbinf, int i, int jt,
                                       int tid) {
    const int to = tid & 7;
    const int tj = tid >> 3;
    const int ob = to * 8;
    const int j0 = tj * 2;
    unsigned long long acc0[4], acc1[4];
#pragma unroll
    for (int p = 0; p < 4; p++) { acc0[p] = 0ull; acc1[p] = 0ull; }

    const float4* r0 = reinterpret_cast<const float4*>(IN + j0 * ZST);
    const float4* r1 = reinterpret_cast<const float4*>(IN + (j0 + 1) * ZST);
#pragma unroll 4
    for (int k4 = 0; k4 < 16; k4++) {
        float4 a0 = r0[k4];
        float4 a1 = r1[k4];
        const float* wbase = Wp + k4 * 256 + to * 4;
#pragma unroll
        for (int kk = 0; kk < 4; kk++) {
            ulonglong2 wa = *reinterpret_cast<const ulonglong2*>(wbase + kk * 64);
            ulonglong2 wb = *reinterpret_cast<const ulonglong2*>(wbase + kk * 64 + 32);
            float e0 = (&a0.x)[kk];
            float e1 = (&a1.x)[kk];
            unsigned long long p0 = pack2(e0, e0);
            unsigned long long p1 = pack2(e1, e1);
            fma2(acc0[0], p0, wa.x); fma2(acc0[1], p0, wa.y);
            fma2(acc0[2], p0, wb.x); fma2(acc0[3], p0, wb.y);
            fma2(acc1[0], p1, wa.x); fma2(acc1[1], p1, wa.y);
            fma2(acc1[2], p1, wb.x); fma2(acc1[3], p1, wb.y);
        }
    }
    float o0[8], o1[8];
#pragma unroll
    for (int p = 0; p < 4; p++) {
        float lo, hi;
        unpack2(acc0[p], lo, hi);
        o0[2 * p]     = siluf_(lo + bias[ob + 2 * p]);
        o0[2 * p + 1] = siluf_(hi + bias[ob + 2 * p + 1]);
        unpack2(acc1[p], lo, hi);
        o1[2 * p]     = siluf_(lo + bias[ob + 2 * p]);
        o1[2 * p + 1] = siluf_(hi + bias[ob + 2 * p + 1]);
    }
    float4* s0 = reinterpret_cast<float4*>(OUT + j0 * ZST + ob);
    float4* s1 = reinterpret_cast<float4*>(OUT + (j0 + 1) * ZST + ob);
    s0[0] = make_float4(o0[0], o0[1], o0[2], o0[3]);
    s0[1] = make_float4(o0[4], o0[5], o0[6], o0[7]);
    s1[0] = make_float4(o1[0], o1[1], o1[2], o1[3]);
    s1[1] = make_float4(o1[4], o1[5], o1[6], o1[7]);
    if (EPRE) {
        float d0 = 0.f, d1 = 0.f;
#pragma unroll
        for (int p = 0; p < 8; p++) {
            float w = winf[ob + p];
            d0 += o0[p] * w;
            d1 += o1[p] * w;
        }
#pragma unroll
        for (int s = 1; s < 8; s <<= 1) {
            d0 += __shfl_xor_sync(0xffffffffu, d0, s);
            d1 += __shfl_xor_sync(0xffffffffu, d1, s);
        }
        if (to == 0) {
            float v0 = sigmoidf_(d0 + rbinf);
            float v1 = sigmoidf_(d1 + rbinf);
            if (jt + j0 == i) v0 = 0.0f;
            if (jt + j0 + 1 == i) v1 = 0.0f;
            e_buf[j0] = v0;
            e_buf[j0 + 1] = v1;
        }
    }
}

// ---------------- main fused pair kernel ----------------
__global__ void __launch_bounds__(256, 2)
egcl_main(const float* __restrict__ x,
          const float* __restrict__ we0,
          const float* __restrict__ we1, const float* __restrict__ be1,
          const float* __restrict__ winf, const float* __restrict__ binf,
          const float* __restrict__ wx0, const float* __restrict__ bx0,
          const float* __restrict__ wx1, const float* __restrict__ bx1,
          const float* __restrict__ wx2, const float* __restrict__ bx2,
          float* __restrict__ out) {
    extern __shared__ float sm[];
    const int i = blockIdx.x;
    const int tid = threadIdx.x;

    // load + permute weights
    for (int t = tid; t < 4096; t += 256) {
        int k = t >> 6, o = t & 63;
        int pos = k * 64 + wperm(o);
        sm[O_W1 + pos]  = we1[t];
        sm[O_WX0 + pos] = wx0[t];
        sm[O_WX1 + pos] = wx1[t];
    }
    {   // wx2 transposed [4][64]
        int k = tid >> 2, hh = tid & 3;
        sm[O_WX2T + hh * 64 + k] = wx2[tid];
        sm[O_WE0H + tid] = we0[tid];   // first 4 rows of we0
    }
    if (tid < 64) {
        sm[O_WINF + tid] = winf[tid];
        sm[O_BE1 + tid]  = be1[tid];
        sm[O_BX0 + tid]  = bx0[tid];
        sm[O_BX1 + tid]  = bx1[tid];
        sm[O_C + tid]    = g_C[i * 64 + tid];
        sm[O_M + tid]    = 0.0f;
    }
    if (tid < 4) sm[O_BX2 + tid] = bx2[tid];

    // per-thread register constants
    const float rbinf = binf[0];
    float xi[12];
#pragma unroll
    for (int t = 0; t < 12; t++) xi[t] = __ldg(x + i * 12 + t);
    __syncthreads();

    const int to = tid & 7;
    const int tj = tid >> 3;
    const int ob = to * 8;
    const int j0 = tj * 2;
    const int jslot = tid >> 2;       // phi_x2 mapping
    const int my_h  = tid & 3;

    // C[i] slice in registers for phi_e0
    float4 c0 = *reinterpret_cast<const float4*>(sm + O_C + ob);
    float4 c1 = *reinterpret_cast<const float4*>(sm + O_C + ob + 4);

    float acc3_0 = 0.f, acc3_1 = 0.f, acc3_2 = 0.f;

    for (int tile = 0; tile < NTILES; tile++) {
        const int jt = tile * TJ;

        // phi_e0 decomposed: B0[j] = silu(G[j] + C[i] + sqn(i,j)@We0[0:4])
        // sqn computed in-register from global x.
#pragma unroll
        for (int jj = 0; jj < 2; jj++) {
            int j = j0 + jj;
            const float4* xr = reinterpret_cast<const float4*>(x + (jt + j) * 12);
            float4 f0 = __ldg(xr), f1 = __ldg(xr + 1), f2 = __ldg(xr + 2);
            float xj[12] = {f0.x, f0.y, f0.z, f0.w, f1.x, f1.y, f1.z, f1.w,
                            f2.x, f2.y, f2.z, f2.w};
            float sq[4];
#pragma unroll
            for (int hh = 0; hh < 4; hh++) {
                float dx = xj[hh * 3 + 0] - xi[hh * 3 + 0];
                float dy = xj[hh * 3 + 1] - xi[hh * 3 + 1];
                float dz = xj[hh * 3 + 2] - xi[hh * 3 + 2];
                sq[hh] = dx * dx + dy * dy + dz * dz;
            }
            float4 gA = __ldg(reinterpret_cast<const float4*>(g_G + (jt + j) * 64 + ob));
            float4 gB = __ldg(reinterpret_cast<const float4*>(g_G + (jt + j) * 64 + ob + 4));
            float pre[8];
            pre[0] = gA.x + c0.x; pre[1] = gA.y + c0.y;
            pre[2] = gA.z + c0.z; pre[3] = gA.w + c0.w;
            pre[4] = gB.x + c1.x; pre[5] = gB.y + c1.y;
            pre[6] = gB.z + c1.z; pre[7] = gB.w + c1.w;
#pragma unroll
            for (int hh = 0; hh < 4; hh++) {
                float s = sq[hh];
                float4 wA = *reinterpret_cast<const float4*>(sm + O_WE0H + hh * 64 + ob);
                float4 wB = *reinterpret_cast<const float4*>(sm + O_WE0H + hh * 64 + ob + 4);
                pre[0] += s * wA.x; pre[1] += s * wA.y;
                pre[2] += s * wA.z; pre[3] += s * wA.w;
                pre[4] += s * wB.x; pre[5] += s * wB.y;
                pre[6] += s * wB.z; pre[7] += s * wB.w;
            }
            float4* st = reinterpret_cast<float4*>(sm + O_B0 + j * ZST + ob);
            st[0] = make_float4(siluf_(pre[0]), siluf_(pre[1]), siluf_(pre[2]), siluf_(pre[3]));
            st[1] = make_float4(siluf_(pre[4]), siluf_(pre[5]), siluf_(pre[6]), siluf_(pre[7]));
        }
        __syncthreads();

        // phi_e1: B0 -> B1 (m_ij), fused phi_inf + sigmoid + mask -> E
        gemm64<true>(sm + O_W1, sm + O_BE1, sm + O_B0, sm + O_B1,
                     sm + O_E, sm + O_WINF, rbinf, i, jt, tid);
        __syncthreads();

        // m_i partials (reads B1,E) + phi_x0 (reads B1 -> B0)
        {
            int o = tid & 63, seg = tid >> 6;
            float p = 0.f;
#pragma unroll 4
            for (int jj = 0; jj < 16; jj++) {
                int j = seg * 16 + jj;
                p += sm[O_E + j] * sm[O_B1 + j * ZST + o];
            }
            sm[O_MP + seg * 64 + o] = p;
        }
        gemm64<false>(sm + O_WX0, sm + O_BX0, sm + O_B1, sm + O_B0,
                      nullptr, nullptr, 0.f, 0, 0, tid);
        __syncthreads();

        // reduce m_i partials; phi_x1: B0 -> B1
        if (tid < 64) {
            sm[O_M + tid] += sm[O_MP + tid] + sm[O_MP + 64 + tid]
                           + sm[O_MP + 128 + tid] + sm[O_MP + 192 + tid];
        }
        gemm64<false>(sm + O_WX1, sm + O_BX1, sm + O_B0, sm + O_B1,
                      nullptr, nullptr, 0.f, 0, 0, tid);
        __syncthreads();

        // phi_x2 (64->4, vectorized) + equivariant shift accumulation
        {
            float d = sm[O_BX2 + my_h];
            const float4* rr = reinterpret_cast<const float4*>(sm + O_B1 + jslot * ZST);
            const float4* ww = reinterpret_cast<const float4*>(sm + O_WX2T + my_h * 64);
            float dot = 0.f;
#pragma unroll 4
            for (int k4 = 0; k4 < 16; k4++) {
                float4 r = rr[k4], w = ww[k4];
                dot += r.x * w.x + r.y * w.y + r.z * w.z + r.w * w.w;
            }
            d += dot;
            const float* xa = x + (jt + jslot) * 12 + my_h * 3;
            float dx = __ldg(xa + 0) - xi[my_h * 3 + 0];
            float dy = __ldg(xa + 1) - xi[my_h * 3 + 1];
            float dz = __ldg(xa + 2) - xi[my_h * 3 + 2];
            float sq = dx * dx + dy * dy + dz * dz;
            float sp = (sq == 0.f) ? 1.f : sq;
            float nrm = sp * rsqf_(sp) + 1.f;   // sqrt(sp) + 1
            float c = d * rcpf_(nrm);
            if (jt + jslot == i) c = 0.f;
            acc3_0 += c * dx;
            acc3_1 += c * dy;
            acc3_2 += c * dz;
        }
        // NOTE: no trailing barrier — these B1/E reads occur before this thread's
        // next-tile phi_e0 barrier, and the only subsequent B1/E writers (phi_e1)
        // run after that barrier, so ordering is sound.
    }

    // finalize m_i
    if (tid < 64) g_mi[i * 64 + tid] = sm[O_M + tid] * (1.0f / sqrtf(767.0f));

    // reduce shift partials -> x_new
    __syncthreads();
    sm[O_SP + tid * 3 + 0] = acc3_0;
    sm[O_SP + tid * 3 + 1] = acc3_1;
    sm[O_SP + tid * 3 + 2] = acc3_2;
    __syncthreads();
    if (tid < 12) {
        int hh = tid / 3, d = tid - hh * 3;
        float s = 0.f;
#pragma unroll 8
        for (int js = 0; js < 64; js++) s += sm[O_SP + (js * 4 + hh) * 3 + d];
        out[i * 12 + hh * 3 + d] = xi[hh * 3 + d] + s * (1.0f / 767.0f);
    }
}

// ---------------- phi_h per node ----------------
__global__ void phi_h_kernel(const float* __restrict__ h,
                             const float* __restrict__ w0, const float* __restrict__ b0,
                             const float* __restrict__ w1, const float* __restrict__ b1,
                             const float* __restrict__ w2, const float* __restrict__ b2,
                             float* __restrict__ out) {
    __shared__ float in1[128], t0[64], t1[64];
    const int i = blockIdx.x;
    const int o = threadIdx.x;  // 64 threads
    in1[o] = g_mi[i * 64 + o];
    in1[64 + o] = h[i * 64 + o];
    __syncthreads();
    float a = b0[o];
#pragma unroll 4
    for (int k = 0; k < 128; k++) a += in1[k] * w0[k * 64 + o];
    t0[o] = siluf_(a);
    __syncthreads();
    a = b1[o];
#pragma unroll 4
    for (int k = 0; k < 64; k++) a += t0[k] * w1[k * 64 + o];
    t1[o] = siluf_(a);
    __syncthreads();
    a = b2[o];
#pragma unroll 4
    for (int k = 0; k < 64; k++) a += t1[k] * w2[k * 64 + o];
    out[NN * 12 + i * 64 + o] = h[i * 64 + o] + a;
}

extern "C" void kernel_launch(void* const* d_in, const int* in_sizes, int n_in,
                              void* d_out, int out_size) {
    const float* x    = (const float*)d_in[0];
    const float* h    = (const float*)d_in[1];
    const float* we0  = (const float*)d_in[2];
    const float* be0  = (const float*)d_in[3];
    const float* we1  = (const float*)d_in[4];
    const float* be1  = (const float*)d_in[5];
    const float* winf = (const float*)d_in[6];
    const float* binf = (const float*)d_in[7];
    const float* wx0  = (const float*)d_in[8];
    const float* bx0  = (const float*)d_in[9];
    const float* wx1  = (const float*)d_in[10];
    const float* bx1  = (const float*)d_in[11];
    const float* wx2  = (const float*)d_in[12];
    const float* bx2  = (const float*)d_in[13];
    const float* wh0  = (const float*)d_in[14];
    const float* bh0  = (const float*)d_in[15];
    const float* wh1  = (const float*)d_in[16];
    const float* bh1  = (const float*)d_in[17];
    const float* wh2  = (const float*)d_in[18];
    const float* bh2  = (const float*)d_in[19];
    float* out = (float*)d_out;

    cudaFuncSetAttribute(egcl_main, cudaFuncAttributeMaxDynamicSharedMemorySize, SMEM_BYTES);

    prep_kernel<<<NN, 128>>>(x, h, we0, be0);
    egcl_main<<<NN, 256, SMEM_BYTES>>>(x, we0, we1, be1, winf, binf,
                                       wx0, bx0, wx1, bx1, wx2, bx2, out);
    phi_h_kernel<<<NN, 64>>>(h, wh0, bh0, wh1, bh1, wh2, bh2, out);
}

// round 13
// speedup vs baseline: 5.7605x; 2.9202x over previous
#include <cuda_runtime.h>
#include <math.h>
#include <stdint.h>

// ---------------- problem constants ----------------
#define NN 768
#define NTILES 6              // 768 / 128
#define LOG2E 1.4426950408889634f

// ---------------- smem layout (bytes) ----------------
// A staging: 128 rows x 64 bf16 per plane (128B/row), hi + lo planes
#define OB_A    1024
#define OB_AL   (OB_A + 16384)
#define OB_W1   (OB_A + 32768)    // each weight: hi plane 8192B, lo at +8192
#define OB_WX0  (OB_W1 + 16384)
#define OB_WX1  (OB_WX0 + 16384)
#define OB_MISC (OB_WX1 + 16384)
// misc float indices
#define MF_WE0H 0      // we0 rows 0..3 [4][64]
#define MF_WX2  256    // wx2 raw [64][4]
#define MF_WINF 512
#define MF_BE1  576
#define MF_BX0  640
#define MF_BX1  704
#define MF_BX2  768    // [4]
#define MF_C    772    // [64]
#define MISC_FLOATS 840
#define SMEM_BYTES (OB_MISC + MISC_FLOATS*4 + 64)

// scratch (no cudaMalloc allowed)
__device__ float g_G[NN * 64];   // hc_j @ We0[4:84] + be0
__device__ float g_C[NN * 64];   // hc_i @ We0[84:164]
__device__ float g_mi[NN * 64];

// ---------------- helpers ----------------
__device__ __forceinline__ uint32_t smem_u32(const void* p) {
    uint32_t a;
    asm("{ .reg .u64 t; cvta.to.shared.u64 t, %1; cvt.u32.u64 %0, t; }"
        : "=r"(a) : "l"(p));
    return a;
}
__device__ __forceinline__ float rcpf_(float x) {
    float r; asm("rcp.approx.ftz.f32 %0, %1;" : "=f"(r) : "f"(x)); return r;
}
__device__ __forceinline__ float ex2f_(float x) {
    float r; asm("ex2.approx.ftz.f32 %0, %1;" : "=f"(r) : "f"(x)); return r;
}
__device__ __forceinline__ float rsqf_(float x) {
    float r; asm("rsqrt.approx.ftz.f32 %0, %1;" : "=f"(r) : "f"(x)); return r;
}
__device__ __forceinline__ float sigmoidf_(float x) { return rcpf_(1.0f + ex2f_(-x * LOG2E)); }
__device__ __forceinline__ float siluf_(float x)    { return x * rcpf_(1.0f + ex2f_(-x * LOG2E)); }

// pack (lo,hi) f32 -> bf16x2; low 16 bits = first arg
__device__ __forceinline__ uint32_t cvtpk(float lo, float hi) {
    uint32_t d;
    asm("cvt.rn.bf16x2.f32 %0, %1, %2;" : "=r"(d) : "f"(hi), "f"(lo));
    return d;
}
__device__ __forceinline__ float bf_lo_f32(uint32_t d) { return __uint_as_float(d << 16); }
__device__ __forceinline__ float bf_hi_f32(uint32_t d) { return __uint_as_float(d & 0xFFFF0000u); }

// row-swizzled byte offset inside a [row][128B] tile (16B-chunk XOR)
#define SWZ(row, kb) ((uint32_t)((row) * 128 + ((kb) ^ (((row) & 7) << 4))))

__device__ __forceinline__ void ldsm4(uint32_t* r, uint32_t addr) {
    asm volatile("ldmatrix.sync.aligned.m8n8.x4.shared.b16 {%0,%1,%2,%3}, [%4];"
        : "=r"(r[0]), "=r"(r[1]), "=r"(r[2]), "=r"(r[3]) : "r"(addr));
}
__device__ __forceinline__ void mma16816(float* c, const uint32_t* a, const uint32_t* b) {
    asm volatile("mma.sync.aligned.m16n8k16.row.col.f32.bf16.bf16.f32 "
        "{%0,%1,%2,%3}, {%4,%5,%6,%7}, {%8,%9}, {%0,%1,%2,%3};"
        : "+f"(c[0]), "+f"(c[1]), "+f"(c[2]), "+f"(c[3])
        : "r"(a[0]), "r"(a[1]), "r"(a[2]), "r"(a[3]), "r"(b[0]), "r"(b[1]));
}
#define STS128(a, r0, r1, r2, r3) \
    asm volatile("st.shared.v4.b32 [%0], {%1, %2, %3, %4};" :: "r"(a), "r"(r0), "r"(r1), "r"(r2), "r"(r3) : "memory")
#define STS32(a, r0) \
    asm volatile("st.shared.b32 [%0], %1;" :: "r"(a), "r"(r0) : "memory")

// ---------------- prep: G[m]=hc_m@We0[4:84]+be0, C[m]=hc_m@We0[84:164] ----------------
__global__ void prep_kernel(const float* __restrict__ x, const float* __restrict__ h,
                            const float* __restrict__ we0, const float* __restrict__ be0) {
    __shared__ float hc[80];
    const int m = blockIdx.x;
    const int t = threadIdx.x;  // 128
    if (t < 64) {
        hc[t] = h[m * 64 + t];
    } else if (t < 80) {
        int p = t - 64;
        int a = p >> 2, b = p & 3;
        const float* xr = x + m * 12;
        float dx = xr[b * 3 + 0] - xr[a * 3 + 0];
        float dy = xr[b * 3 + 1] - xr[a * 3 + 1];
        float dz = xr[b * 3 + 2] - xr[a * 3 + 2];
        hc[t] = dx * dx + dy * dy + dz * dz;
    }
    __syncthreads();
    const int o = t & 63;
    const float* W = we0 + ((t < 64) ? 4 * 64 : 84 * 64);
    float a = (t < 64) ? be0[o] : 0.0f;
#pragma unroll 8
    for (int k = 0; k < 80; k++) a += hc[k] * W[k * 64 + o];
    if (t < 64) g_G[m * 64 + o] = a;
    else        g_C[m * 64 + o] = a;
}

// store W[k][o] (64x64 f32) as [o][k] bf16 hi/lo planes, swizzled
__device__ __forceinline__ void fill_wtile(uint32_t sb, uint32_t wof,
                                           const float* __restrict__ W, int tid) {
    for (int t = tid; t < 2048; t += 128) {
        int o = t >> 5;
        int kp = (t & 31) * 2;
        float v0 = __ldg(W + kp * 64 + o);
        float v1 = __ldg(W + (kp + 1) * 64 + o);
        uint32_t hp = cvtpk(v0, v1);
        uint32_t lp = cvtpk(v0 - bf_lo_f32(hp), v1 - bf_hi_f32(hp));
        uint32_t ub = wof + SWZ(o, kp * 2);
        STS32(sb + ub, hp);
        STS32(sb + ub + 8192, lp);
    }
}

// one bf16x3-split GEMM from register A-frags: acc[2][8][4] += A(128x64) @ W(64->64)
__device__ __forceinline__ void gemm_regs(float acc[2][8][4],
                                          const uint32_t Ah[2][4][4],
                                          const uint32_t Al[2][4][4],
                                          uint32_t wbase, int lane) {
    const uint32_t nrow_lo = (lane & 7) + ((lane & 16) >> 1);
    const uint32_t kb_off = (lane & 8) << 1;
#pragma unroll
    for (int kt = 0; kt < 4; kt++) {
#pragma unroll
        for (int ntp = 0; ntp < 4; ntp++) {
            uint32_t nrow = ntp * 16 + nrow_lo;
            uint32_t kb = kt * 32 + kb_off;
            uint32_t ad = wbase + SWZ(nrow, kb);
            uint32_t Bh[4], Bl[4];
            ldsm4(Bh, ad);
            ldsm4(Bl, ad + 8192);
#pragma unroll
            for (int mt = 0; mt < 2; mt++) {
                mma16816(acc[mt][2 * ntp],     Ah[mt][kt], Bh);
                mma16816(acc[mt][2 * ntp],     Ah[mt][kt], Bl);
                mma16816(acc[mt][2 * ntp],     Al[mt][kt], Bh);
                mma16816(acc[mt][2 * ntp + 1], Ah[mt][kt], Bh + 2);
                mma16816(acc[mt][2 * ntp + 1], Ah[mt][kt], Bl + 2);
                mma16816(acc[mt][2 * ntp + 1], Al[mt][kt], Bh + 2);
            }
        }
    }
}

// bias + silu in place on acc
__device__ __forceinline__ void bias_silu(float a[2][8][4], const float* bias, int lr) {
#pragma unroll
    for (int nt = 0; nt < 8; nt++) {
        float2 b = *(const float2*)(bias + nt * 8 + lr * 2);
#pragma unroll
        for (int mt = 0; mt < 2; mt++) {
            a[mt][nt][0] = siluf_(a[mt][nt][0] + b.x);
            a[mt][nt][1] = siluf_(a[mt][nt][1] + b.y);
            a[mt][nt][2] = siluf_(a[mt][nt][2] + b.x);
            a[mt][nt][3] = siluf_(a[mt][nt][3] + b.y);
        }
    }
}

// D fragments -> A fragments for next GEMM (bf16 hi/lo split), pure registers
__device__ __forceinline__ void pack_frags(const float a[2][8][4],
                                           uint32_t Ah[2][4][4], uint32_t Al[2][4][4]) {
#pragma unroll
    for (int mt = 0; mt < 2; mt++) {
#pragma unroll
        for (int kt = 0; kt < 4; kt++) {
            const float* p0 = a[mt][2 * kt];
            const float* p1 = a[mt][2 * kt + 1];
            uint32_t h0 = cvtpk(p0[0], p0[1]);
            uint32_t h1 = cvtpk(p0[2], p0[3]);
            uint32_t h2 = cvtpk(p1[0], p1[1]);
            uint32_t h3 = cvtpk(p1[2], p1[3]);
            Ah[mt][kt][0] = h0;
            Ah[mt][kt][1] = h1;
            Ah[mt][kt][2] = h2;
            Ah[mt][kt][3] = h3;
            Al[mt][kt][0] = cvtpk(p0[0] - bf_lo_f32(h0), p0[1] - bf_hi_f32(h0));
            Al[mt][kt][1] = cvtpk(p0[2] - bf_lo_f32(h1), p0[3] - bf_hi_f32(h1));
            Al[mt][kt][2] = cvtpk(p1[0] - bf_lo_f32(h2), p1[1] - bf_hi_f32(h2));
            Al[mt][kt][3] = cvtpk(p1[2] - bf_lo_f32(h3), p1[3] - bf_hi_f32(h3));
        }
    }
}

// ---------------- main fused pair kernel ----------------
__global__ void __launch_bounds__(128, 2)
egcl_main(const float* __restrict__ x,
          const float* __restrict__ we0,
          const float* __restrict__ we1, const float* __restrict__ be1,
          const float* __restrict__ winf, const float* __restrict__ binf,
          const float* __restrict__ wx0, const float* __restrict__ bx0,
          const float* __restrict__ wx1, const float* __restrict__ bx1,
          const float* __restrict__ wx2, const float* __restrict__ bx2,
          float* __restrict__ out) {
    extern __shared__ char smem[];
    const uint32_t sb = smem_u32(smem);
    float* msc = (float*)(smem + OB_MISC);
    const int i = blockIdx.x;
    const int tid = threadIdx.x;   // 128
    const int lane = tid & 31;
    const int wid = tid >> 5;
    const int lq = lane >> 2;      // 0..7
    const int lr = lane & 3;       // 0..3
    const int rb = wid * 32;       // warp row base in 128-row tile

    fill_wtile(sb, OB_W1,  we1, tid);
    fill_wtile(sb, OB_WX0, wx0, tid);
    fill_wtile(sb, OB_WX1, wx1, tid);
    msc[MF_WE0H + tid]       = we0[tid];
    msc[MF_WE0H + 128 + tid] = we0[128 + tid];
    msc[MF_WX2 + tid]        = wx2[tid];
    msc[MF_WX2 + 128 + tid]  = wx2[128 + tid];
    if (tid < 64) {
        msc[MF_WINF + tid] = winf[tid];
        msc[MF_BE1 + tid]  = be1[tid];
        msc[MF_BX0 + tid]  = bx0[tid];
        msc[MF_BX1 + tid]  = bx1[tid];
        msc[MF_C + tid]    = g_C[i * 64 + tid];
    }
    if (tid < 4) msc[MF_BX2 + tid] = bx2[tid];

    const float rbinf = __ldg(binf);
    float xi[12];
#pragma unroll
    for (int t = 0; t < 12; t++) xi[t] = __ldg(x + i * 12 + t);
    __syncthreads();

    float acc_mi[8][2];
#pragma unroll
    for (int nt = 0; nt < 8; nt++) { acc_mi[nt][0] = 0.f; acc_mi[nt][1] = 0.f; }
    float sh0 = 0.f, sh1 = 0.f, sh2 = 0.f;

    for (int tile = 0; tile < NTILES; tile++) {
        // ---- Phase A: build GEMM1 A = split(silu(G[j] + C + sqn @ We0h)), row = tid ----
        {
            const int j2 = tile * 128 + tid;
            const float4* xr = (const float4*)(x + j2 * 12);
            float4 f0 = __ldg(xr), f1 = __ldg(xr + 1), f2 = __ldg(xr + 2);
            float xj[12] = {f0.x, f0.y, f0.z, f0.w, f1.x, f1.y, f1.z, f1.w,
                            f2.x, f2.y, f2.z, f2.w};
            float sq[4];
#pragma unroll
            for (int hh = 0; hh < 4; hh++) {
                float dx = xj[hh * 3 + 0] - xi[hh * 3 + 0];
                float dy = xj[hh * 3 + 1] - xi[hh * 3 + 1];
                float dz = xj[hh * 3 + 2] - xi[hh * 3 + 2];
                sq[hh] = dx * dx + dy * dy + dz * dz;
            }
            const float4* gg = (const float4*)(g_G + j2 * 64);
            const uint32_t swz = (uint32_t)((tid & 7) << 4);
#pragma unroll
            for (int c = 0; c < 8; c++) {
                float4 gA = __ldg(gg + 2 * c);
                float4 gB = __ldg(gg + 2 * c + 1);
                float v[8] = {gA.x, gA.y, gA.z, gA.w, gB.x, gB.y, gB.z, gB.w};
#pragma unroll
                for (int p = 0; p < 8; p++) {
                    int o = c * 8 + p;
                    float pre = v[p] + msc[MF_C + o];
#pragma unroll
                    for (int hh = 0; hh < 4; hh++)
                        pre += sq[hh] * msc[MF_WE0H + hh * 64 + o];
                    v[p] = siluf_(pre);
                }
                uint32_t hi[4], lo[4];
#pragma unroll
                for (int p = 0; p < 4; p++) {
                    uint32_t h = cvtpk(v[2 * p], v[2 * p + 1]);
                    hi[p] = h;
                    lo[p] = cvtpk(v[2 * p] - bf_lo_f32(h), v[2 * p + 1] - bf_hi_f32(h));
                }
                uint32_t ad = sb + OB_A + tid * 128 + (((uint32_t)(c * 16)) ^ swz);
                STS128(ad, hi[0], hi[1], hi[2], hi[3]);
                STS128(ad + 16384, lo[0], lo[1], lo[2], lo[3]);
            }
        }
        __syncthreads();

        // ---- load A fragments for GEMM1 ----
        uint32_t Ah[2][4][4], Al[2][4][4];
        {
            const uint32_t rlo = (uint32_t)(lane & 15);
            const uint32_t khalf = (uint32_t)(lane & 16);
#pragma unroll
            for (int mt = 0; mt < 2; mt++)
#pragma unroll
                for (int kt = 0; kt < 4; kt++) {
                    uint32_t ad = sb + OB_A + SWZ(rb + mt * 16 + rlo, kt * 32 + khalf);
                    ldsm4(Ah[mt][kt], ad);
                    ldsm4(Al[mt][kt], ad + 16384);
                }
        }
        __syncthreads();   // all A-staging reads done before next tile's phase A

        float acc[2][8][4];
#pragma unroll
        for (int mt = 0; mt < 2; mt++)
#pragma unroll
            for (int nt = 0; nt < 8; nt++)
#pragma unroll
                for (int q = 0; q < 4; q++) acc[mt][nt][q] = 0.f;

        // ---- GEMM1: m_ij = silu(A @ We1 + be1); fused phi_inf / e / m_i ----
        gemm_regs(acc, Ah, Al, sb + OB_W1, lane);
        bias_silu(acc, msc + MF_BE1, lr);
        {
            float e[2][2];
#pragma unroll
            for (int mt = 0; mt < 2; mt++) {
                float d0 = 0.f, d1 = 0.f;
#pragma unroll
                for (int nt = 0; nt < 8; nt++) {
                    float2 wf = *(const float2*)(msc + MF_WINF + nt * 8 + lr * 2);
                    d0 += acc[mt][nt][0] * wf.x + acc[mt][nt][1] * wf.y;
                    d1 += acc[mt][nt][2] * wf.x + acc[mt][nt][3] * wf.y;
                }
                d0 += __shfl_xor_sync(0xffffffffu, d0, 1);
                d0 += __shfl_xor_sync(0xffffffffu, d0, 2);
                d1 += __shfl_xor_sync(0xffffffffu, d1, 1);
                d1 += __shfl_xor_sync(0xffffffffu, d1, 2);
                int j0 = tile * 128 + rb + mt * 16 + lq;
                float e0 = sigmoidf_(d0 + rbinf);
                float e1 = sigmoidf_(d1 + rbinf);
                if (j0 == i) e0 = 0.f;
                if (j0 + 8 == i) e1 = 0.f;
                e[mt][0] = e0;
                e[mt][1] = e1;
            }
#pragma unroll
            for (int mt = 0; mt < 2; mt++)
#pragma unroll
                for (int nt = 0; nt < 8; nt++) {
                    acc_mi[nt][0] += e[mt][0] * acc[mt][nt][0] + e[mt][1] * acc[mt][nt][2];
                    acc_mi[nt][1] += e[mt][0] * acc[mt][nt][1] + e[mt][1] * acc[mt][nt][3];
                }
        }
        pack_frags(acc, Ah, Al);

        // ---- GEMM2: t0 = silu(m_ij @ Wx0 + bx0) ----
#pragma unroll
        for (int mt = 0; mt < 2; mt++)
#pragma unroll
            for (int nt = 0; nt < 8; nt++)
#pragma unroll
                for (int q = 0; q < 4; q++) acc[mt][nt][q] = 0.f;
        gemm_regs(acc, Ah, Al, sb + OB_WX0, lane);
        bias_silu(acc, msc + MF_BX0, lr);
        pack_frags(acc, Ah, Al);

        // ---- GEMM3: t1 = silu(t0 @ Wx1 + bx1); phi_x2 + shift ----
#pragma unroll
        for (int mt = 0; mt < 2; mt++)
#pragma unroll
            for (int nt = 0; nt < 8; nt++)
#pragma unroll
                for (int q = 0; q < 4; q++) acc[mt][nt][q] = 0.f;
        gemm_regs(acc, Ah, Al, sb + OB_WX1, lane);
        bias_silu(acc, msc + MF_BX1, lr);
        {
            float part[4][4];
#pragma unroll
            for (int r = 0; r < 4; r++)
#pragma unroll
                for (int hh = 0; hh < 4; hh++) part[r][hh] = 0.f;
#pragma unroll
            for (int nt = 0; nt < 8; nt++)
#pragma unroll
                for (int qp = 0; qp < 2; qp++) {
                    int c = nt * 8 + lr * 2 + qp;
                    float4 w4 = *(const float4*)(msc + MF_WX2 + c * 4);
#pragma unroll
                    for (int mt = 0; mt < 2; mt++) {
                        float v0 = acc[mt][nt][qp];
                        float v1 = acc[mt][nt][2 + qp];
                        part[2 * mt][0] += v0 * w4.x;  part[2 * mt][1] += v0 * w4.y;
                        part[2 * mt][2] += v0 * w4.z;  part[2 * mt][3] += v0 * w4.w;
                        part[2 * mt + 1][0] += v1 * w4.x;  part[2 * mt + 1][1] += v1 * w4.y;
                        part[2 * mt + 1][2] += v1 * w4.z;  part[2 * mt + 1][3] += v1 * w4.w;
                    }
                }
#pragma unroll
            for (int r = 0; r < 4; r++)
#pragma unroll
                for (int hh = 0; hh < 4; hh++) {
                    part[r][hh] += __shfl_xor_sync(0xffffffffu, part[r][hh], 1);
                    part[r][hh] += __shfl_xor_sync(0xffffffffu, part[r][hh], 2);
                }
            const float bxh = msc[MF_BX2 + lr];
            const float xih0 = xi[lr * 3 + 0], xih1 = xi[lr * 3 + 1], xih2 = xi[lr * 3 + 2];
#pragma unroll
            for (int mt = 0; mt < 2; mt++)
#pragma unroll
                for (int half = 0; half < 2; half++) {
                    int row = rb + mt * 16 + lq + half * 8;
                    int j = tile * 128 + row;
                    float d = part[2 * mt + half][lr] + bxh;
                    const float* xa = x + j * 12 + lr * 3;
                    float dx = __ldg(xa + 0) - xih0;
                    float dy = __ldg(xa + 1) - xih1;
                    float dz = __ldg(xa + 2) - xih2;
                    float sqn = dx * dx + dy * dy + dz * dz;
                    float sp = (sqn == 0.f) ? 1.f : sqn;
                    float nrm = sp * rsqf_(sp) + 1.f;   // sqrt(sp)+1
                    float cc = d * rcpf_(nrm);
                    if (j == i) cc = 0.f;
                    sh0 += cc * dx;
                    sh1 += cc * dy;
                    sh2 += cc * dz;
                }
        }
    }

    // ---- reductions (reuse A staging smem) ----
    float* st = (float*)(smem + OB_A);
    __syncthreads();
#pragma unroll
    for (int nt = 0; nt < 8; nt++) {
        st[tid * 16 + nt * 2 + 0] = acc_mi[nt][0];
        st[tid * 16 + nt * 2 + 1] = acc_mi[nt][1];
    }
    __syncthreads();
    if (tid < 64) {
        int nt = tid >> 3, l4 = (tid & 7) >> 1, q = tid & 1;
        float s = 0.f;
#pragma unroll 8
        for (int g = 0; g < 32; g++) s += st[(g * 4 + l4) * 16 + nt * 2 + q];
        g_mi[i * 64 + tid] = s * (1.0f / sqrtf(767.0f));
    }
    __syncthreads();
    st[tid * 3 + 0] = sh0;
    st[tid * 3 + 1] = sh1;
    st[tid * 3 + 2] = sh2;
    __syncthreads();
    if (tid < 12) {
        int hh = tid / 3, d = tid - hh * 3;
        float s = 0.f;
#pragma unroll 8
        for (int g = 0; g < 32; g++) s += st[(g * 4 + hh) * 3 + d];
        out[i * 12 + tid] = xi[tid] + s * (1.0f / 767.0f);
    }
}

// ---------------- phi_h per node ----------------
__global__ void phi_h_kernel(const float* __restrict__ h,
                             const float* __restrict__ w0, const float* __restrict__ b0,
                             const float* __restrict__ w1, const float* __restrict__ b1,
                             const float* __restrict__ w2, const float* __restrict__ b2,
                             float* __restrict__ out) {
    __shared__ float in1[128], t0[64], t1[64];
    const int i = blockIdx.x;
    const int o = threadIdx.x;  // 64
    in1[o] = g_mi[i * 64 + o];
    in1[64 + o] = h[i * 64 + o];
    __syncthreads();
    float a = b0[o];
#pragma unroll 4
    for (int k = 0; k < 128; k++) a += in1[k] * w0[k * 64 + o];
    t0[o] = siluf_(a);
    __syncthreads();
    a = b1[o];
#pragma unroll 4
    for (int k = 0; k < 64; k++) a += t0[k] * w1[k * 64 + o];
    t1[o] = siluf_(a);
    __syncthreads();
    a = b2[o];
#pragma unroll 4
    for (int k = 0; k < 64; k++) a += t1[k] * w2[k * 64 + o];
    out[NN * 12 + i * 64 + o] = h[i * 64 + o] + a;
}

extern "C" void kernel_launch(void* const* d_in, const int* in_sizes, int n_in,
                              void* d_out, int out_size) {
    const float* x    = (const float*)d_in[0];
    const float* h    = (const float*)d_in[1];
    const float* we0  = (const float*)d_in[2];
    const float* be0  = (const float*)d_in[3];
    const float* we1  = (const float*)d_in[4];
    const float* be1  = (const float*)d_in[5];
    const float* winf = (const float*)d_in[6];
    const float* binf = (const float*)d_in[7];
    const float* wx0  = (const float*)d_in[8];
    const float* bx0  = (const float*)d_in[9];
    const float* wx1  = (const float*)d_in[10];
    const float* bx1  = (const float*)d_in[11];
    const float* wx2  = (const float*)d_in[12];
    const float* bx2  = (const float*)d_in[13];
    const float* wh0  = (const float*)d_in[14];
    const float* bh0  = (const float*)d_in[15];
    const float* wh1  = (const float*)d_in[16];
    const float* bh1  = (const float*)d_in[17];
    const float* wh2  = (const float*)d_in[18];
    const float* bh2  = (const float*)d_in[19];
    float* out = (float*)d_out;

    cudaFuncSetAttribute(egcl_main, cudaFuncAttributeMaxDynamicSharedMemorySize, SMEM_BYTES);

    prep_kernel<<<NN, 128>>>(x, h, we0, be0);
    egcl_main<<<NN, 128, SMEM_BYTES>>>(x, we0, we1, be1, winf, binf,
                                       wx0, bx0, wx1, bx1, wx2, bx2, out);
    phi_h_kernel<<<NN, 64>>>(h, wh0, bh0, wh1, bh1, wh2, bh2, out);
}

// round 14
// speedup vs baseline: 6.5894x; 1.1439x over previous
#include <cuda_runtime.h>
#include <math.h>
#include <stdint.h>

// ---------------- problem constants ----------------
#define NN 768
#define NTILES 6              // 768 / 128
#define LOG2E 1.4426950408889634f

// ---------------- smem layout (bytes) ----------------
// A staging: 128 rows x 64 bf16 per plane (128B/row), hi + lo planes (GEMM1 A is split)
#define OB_A    1024
#define OB_W1   (OB_A + 32768)     // we1: hi plane 8192B + lo plane 8192B
#define OB_WX0  (OB_W1 + 16384)    // wx0: hi plane only (8192B)
#define OB_WX1  (OB_WX0 + 8192)    // wx1: hi plane only (8192B)
#define OB_MISC (OB_WX1 + 8192)
// misc float indices
#define MF_WE0H 0      // we0 rows 0..3 [4][64]
#define MF_WX2  256    // wx2 raw [64][4]
#define MF_WINF 512
#define MF_BE1  576
#define MF_BX0  640
#define MF_BX1  704
#define MF_BX2  768    // [4]
#define MF_C    772    // [64]
#define MISC_FLOATS 840
#define SMEM_BYTES (OB_MISC + MISC_FLOATS*4 + 64)

// scratch (no cudaMalloc allowed)
__device__ float g_G[NN * 64];   // hc_j @ We0[4:84] + be0
__device__ float g_C[NN * 64];   // hc_i @ We0[84:164]
__device__ float g_mi[NN * 64];

// ---------------- helpers ----------------
__device__ __forceinline__ uint32_t smem_u32(const void* p) {
    uint32_t a;
    asm("{ .reg .u64 t; cvta.to.shared.u64 t, %1; cvt.u32.u64 %0, t; }"
        : "=r"(a) : "l"(p));
    return a;
}
__device__ __forceinline__ float rcpf_(float x) {
    float r; asm("rcp.approx.ftz.f32 %0, %1;" : "=f"(r) : "f"(x)); return r;
}
__device__ __forceinline__ float ex2f_(float x) {
    float r; asm("ex2.approx.ftz.f32 %0, %1;" : "=f"(r) : "f"(x)); return r;
}
__device__ __forceinline__ float rsqf_(float x) {
    float r; asm("rsqrt.approx.ftz.f32 %0, %1;" : "=f"(r) : "f"(x)); return r;
}
__device__ __forceinline__ float sigmoidf_(float x) { return rcpf_(1.0f + ex2f_(-x * LOG2E)); }
__device__ __forceinline__ float siluf_(float x)    { return x * rcpf_(1.0f + ex2f_(-x * LOG2E)); }

// pack (lo,hi) f32 -> bf16x2; low 16 bits = first arg
__device__ __forceinline__ uint32_t cvtpk(float lo, float hi) {
    uint32_t d;
    asm("cvt.rn.bf16x2.f32 %0, %1, %2;" : "=r"(d) : "f"(hi), "f"(lo));
    return d;
}
__device__ __forceinline__ float bf_lo_f32(uint32_t d) { return __uint_as_float(d << 16); }
__device__ __forceinline__ float bf_hi_f32(uint32_t d) { return __uint_as_float(d & 0xFFFF0000u); }

// row-swizzled byte offset inside a [row][128B] tile (16B-chunk XOR)
#define SWZ(row, kb) ((uint32_t)((row) * 128 + ((kb) ^ (((row) & 7) << 4))))

__device__ __forceinline__ void ldsm4(uint32_t* r, uint32_t addr) {
    asm volatile("ldmatrix.sync.aligned.m8n8.x4.shared.b16 {%0,%1,%2,%3}, [%4];"
        : "=r"(r[0]), "=r"(r[1]), "=r"(r[2]), "=r"(r[3]) : "r"(addr));
}
__device__ __forceinline__ void mma16816(float* c, const uint32_t* a, const uint32_t* b) {
    asm volatile("mma.sync.aligned.m16n8k16.row.col.f32.bf16.bf16.f32 "
        "{%0,%1,%2,%3}, {%4,%5,%6,%7}, {%8,%9}, {%0,%1,%2,%3};"
        : "+f"(c[0]), "+f"(c[1]), "+f"(c[2]), "+f"(c[3])
        : "r"(a[0]), "r"(a[1]), "r"(a[2]), "r"(a[3]), "r"(b[0]), "r"(b[1]));
}
#define STS128(a, r0, r1, r2, r3) \
    asm volatile("st.shared.v4.b32 [%0], {%1, %2, %3, %4};" :: "r"(a), "r"(r0), "r"(r1), "r"(r2), "r"(r3) : "memory")
#define STS32(a, r0) \
    asm volatile("st.shared.b32 [%0], %1;" :: "r"(a), "r"(r0) : "memory")

// ---------------- prep: G[m]=hc_m@We0[4:84]+be0, C[m]=hc_m@We0[84:164] ----------------
__global__ void prep_kernel(const float* __restrict__ x, const float* __restrict__ h,
                            const float* __restrict__ we0, const float* __restrict__ be0) {
    __shared__ float hc[80];
    const int m = blockIdx.x;
    const int t = threadIdx.x;  // 128
    if (t < 64) {
        hc[t] = h[m * 64 + t];
    } else if (t < 80) {
        int p = t - 64;
        int a = p >> 2, b = p & 3;
        const float* xr = x + m * 12;
        float dx = xr[b * 3 + 0] - xr[a * 3 + 0];
        float dy = xr[b * 3 + 1] - xr[a * 3 + 1];
        float dz = xr[b * 3 + 2] - xr[a * 3 + 2];
        hc[t] = dx * dx + dy * dy + dz * dz;
    }
    __syncthreads();
    const int o = t & 63;
    const float* W = we0 + ((t < 64) ? 4 * 64 : 84 * 64);
    float a = (t < 64) ? be0[o] : 0.0f;
#pragma unroll 8
    for (int k = 0; k < 80; k++) a += hc[k] * W[k * 64 + o];
    if (t < 64) g_G[m * 64 + o] = a;
    else        g_C[m * 64 + o] = a;
}

// store W[k][o] (64x64 f32) as [o][k] bf16 hi(+lo) planes, swizzled
__device__ __forceinline__ void fill_wtile_split(uint32_t sb, uint32_t wof,
                                                 const float* __restrict__ W, int tid) {
    for (int t = tid; t < 2048; t += 128) {
        int o = t >> 5;
        int kp = (t & 31) * 2;
        float v0 = __ldg(W + kp * 64 + o);
        float v1 = __ldg(W + (kp + 1) * 64 + o);
        uint32_t hp = cvtpk(v0, v1);
        uint32_t lp = cvtpk(v0 - bf_lo_f32(hp), v1 - bf_hi_f32(hp));
        uint32_t ub = wof + SWZ(o, kp * 2);
        STS32(sb + ub, hp);
        STS32(sb + ub + 8192, lp);
    }
}
__device__ __forceinline__ void fill_wtile_hi(uint32_t sb, uint32_t wof,
                                              const float* __restrict__ W, int tid) {
    for (int t = tid; t < 2048; t += 128) {
        int o = t >> 5;
        int kp = (t & 31) * 2;
        float v0 = __ldg(W + kp * 64 + o);
        float v1 = __ldg(W + (kp + 1) * 64 + o);
        STS32(sb + wof + SWZ(o, kp * 2), cvtpk(v0, v1));
    }
}

// 3-split GEMM (GEMM1): acc += A(128x64, hi+lo) @ W(hi+lo)
__device__ __forceinline__ void gemm_split(float acc[2][8][4],
                                           const uint32_t Ah[2][4][4],
                                           const uint32_t Al[2][4][4],
                                           uint32_t wbase, int lane) {
    const uint32_t nrow_lo = (lane & 7) + ((lane & 16) >> 1);
    const uint32_t kb_off = (lane & 8) << 1;
#pragma unroll
    for (int kt = 0; kt < 4; kt++) {
#pragma unroll
        for (int ntp = 0; ntp < 4; ntp++) {
            uint32_t ad = wbase + SWZ(ntp * 16 + nrow_lo, kt * 32 + kb_off);
            uint32_t Bh[4], Bl[4];
            ldsm4(Bh, ad);
            ldsm4(Bl, ad + 8192);
#pragma unroll
            for (int mt = 0; mt < 2; mt++) {
                mma16816(acc[mt][2 * ntp],     Ah[mt][kt], Bh);
                mma16816(acc[mt][2 * ntp],     Ah[mt][kt], Bl);
                mma16816(acc[mt][2 * ntp],     Al[mt][kt], Bh);
                mma16816(acc[mt][2 * ntp + 1], Ah[mt][kt], Bh + 2);
                mma16816(acc[mt][2 * ntp + 1], Ah[mt][kt], Bl + 2);
                mma16816(acc[mt][2 * ntp + 1], Al[mt][kt], Bh + 2);
            }
        }
    }
}

// hi-only GEMM (GEMM2/3, phi_x path): acc += A(hi) @ W(hi)
__device__ __forceinline__ void gemm_hi(float acc[2][8][4],
                                        const uint32_t Ah[2][4][4],
                                        uint32_t wbase, int lane) {
    const uint32_t nrow_lo = (lane & 7) + ((lane & 16) >> 1);
    const uint32_t kb_off = (lane & 8) << 1;
#pragma unroll
    for (int kt = 0; kt < 4; kt++) {
#pragma unroll
        for (int ntp = 0; ntp < 4; ntp++) {
            uint32_t Bh[4];
            ldsm4(Bh, wbase + SWZ(ntp * 16 + nrow_lo, kt * 32 + kb_off));
#pragma unroll
            for (int mt = 0; mt < 2; mt++) {
                mma16816(acc[mt][2 * ntp],     Ah[mt][kt], Bh);
                mma16816(acc[mt][2 * ntp + 1], Ah[mt][kt], Bh + 2);
            }
        }
    }
}

// bias + silu in place on acc
__device__ __forceinline__ void bias_silu(float a[2][8][4], const float* bias, int lr) {
#pragma unroll
    for (int nt = 0; nt < 8; nt++) {
        float2 b = *(const float2*)(bias + nt * 8 + lr * 2);
#pragma unroll
        for (int mt = 0; mt < 2; mt++) {
            a[mt][nt][0] = siluf_(a[mt][nt][0] + b.x);
            a[mt][nt][1] = siluf_(a[mt][nt][1] + b.y);
            a[mt][nt][2] = siluf_(a[mt][nt][2] + b.x);
            a[mt][nt][3] = siluf_(a[mt][nt][3] + b.y);
        }
    }
}

// D fragments -> hi-only A fragments for next GEMM (pure registers)
__device__ __forceinline__ void pack_frags_hi(const float a[2][8][4], uint32_t Ah[2][4][4]) {
#pragma unroll
    for (int mt = 0; mt < 2; mt++)
#pragma unroll
        for (int kt = 0; kt < 4; kt++) {
            const float* p0 = a[mt][2 * kt];
            const float* p1 = a[mt][2 * kt + 1];
            Ah[mt][kt][0] = cvtpk(p0[0], p0[1]);
            Ah[mt][kt][1] = cvtpk(p0[2], p0[3]);
            Ah[mt][kt][2] = cvtpk(p1[0], p1[1]);
            Ah[mt][kt][3] = cvtpk(p1[2], p1[3]);
        }
}

// ---------------- main fused pair kernel ----------------
__global__ void __launch_bounds__(128, 2)
egcl_main(const float* __restrict__ x,
          const float* __restrict__ we0,
          const float* __restrict__ we1, const float* __restrict__ be1,
          const float* __restrict__ winf, const float* __restrict__ binf,
          const float* __restrict__ wx0, const float* __restrict__ bx0,
          const float* __restrict__ wx1, const float* __restrict__ bx1,
          const float* __restrict__ wx2, const float* __restrict__ bx2,
          float* __restrict__ out) {
    extern __shared__ char smem[];
    const uint32_t sb = smem_u32(smem);
    float* msc = (float*)(smem + OB_MISC);
    const int i = blockIdx.x;
    const int tid = threadIdx.x;   // 128
    const int lane = tid & 31;
    const int wid = tid >> 5;
    const int lq = lane >> 2;      // 0..7
    const int lr = lane & 3;       // 0..3
    const int rb = wid * 32;       // warp row base in 128-row tile

    fill_wtile_split(sb, OB_W1, we1, tid);
    fill_wtile_hi(sb, OB_WX0, wx0, tid);
    fill_wtile_hi(sb, OB_WX1, wx1, tid);
    msc[MF_WE0H + tid]       = we0[tid];
    msc[MF_WE0H + 128 + tid] = we0[128 + tid];
    msc[MF_WX2 + tid]        = wx2[tid];
    msc[MF_WX2 + 128 + tid]  = wx2[128 + tid];
    if (tid < 64) {
        msc[MF_WINF + tid] = winf[tid];
        msc[MF_BE1 + tid]  = be1[tid];
        msc[MF_BX0 + tid]  = bx0[tid];
        msc[MF_BX1 + tid]  = bx1[tid];
        msc[MF_C + tid]    = g_C[i * 64 + tid];
    }
    if (tid < 4) msc[MF_BX2 + tid] = bx2[tid];

    const float rbinf = __ldg(binf);
    float xi[12];
#pragma unroll
    for (int t = 0; t < 12; t++) xi[t] = __ldg(x + i * 12 + t);
    __syncthreads();

    float acc_mi[8][2];
#pragma unroll
    for (int nt = 0; nt < 8; nt++) { acc_mi[nt][0] = 0.f; acc_mi[nt][1] = 0.f; }
    float sh0 = 0.f, sh1 = 0.f, sh2 = 0.f;

    for (int tile = 0; tile < NTILES; tile++) {
        // ---- Phase A: build GEMM1 A = split(silu(G[j] + C + sqn @ We0h)), row = tid ----
        {
            const int j2 = tile * 128 + tid;
            const float4* xr = (const float4*)(x + j2 * 12);
            float4 f0 = __ldg(xr), f1 = __ldg(xr + 1), f2 = __ldg(xr + 2);
            float xj[12] = {f0.x, f0.y, f0.z, f0.w, f1.x, f1.y, f1.z, f1.w,
                            f2.x, f2.y, f2.z, f2.w};
            float sq[4];
#pragma unroll
            for (int hh = 0; hh < 4; hh++) {
                float dx = xj[hh * 3 + 0] - xi[hh * 3 + 0];
                float dy = xj[hh * 3 + 1] - xi[hh * 3 + 1];
                float dz = xj[hh * 3 + 2] - xi[hh * 3 + 2];
                sq[hh] = dx * dx + dy * dy + dz * dz;
            }
            const float4* gg = (const float4*)(g_G + j2 * 64);
            const uint32_t swz = (uint32_t)((tid & 7) << 4);
#pragma unroll
            for (int c = 0; c < 8; c++) {
                float4 gA = __ldg(gg + 2 * c);
                float4 gB = __ldg(gg + 2 * c + 1);
                float v[8] = {gA.x, gA.y, gA.z, gA.w, gB.x, gB.y, gB.z, gB.w};
#pragma unroll
                for (int p = 0; p < 8; p++) {
                    int o = c * 8 + p;
                    float pre = v[p] + msc[MF_C + o];
#pragma unroll
                    for (int hh = 0; hh < 4; hh++)
                        pre += sq[hh] * msc[MF_WE0H + hh * 64 + o];
                    v[p] = siluf_(pre);
                }
                uint32_t hi[4], lo[4];
#pragma unroll
                for (int p = 0; p < 4; p++) {
                    uint32_t h = cvtpk(v[2 * p], v[2 * p + 1]);
                    hi[p] = h;
                    lo[p] = cvtpk(v[2 * p] - bf_lo_f32(h), v[2 * p + 1] - bf_hi_f32(h));
                }
                uint32_t ad = sb + OB_A + tid * 128 + (((uint32_t)(c * 16)) ^ swz);
                STS128(ad, hi[0], hi[1], hi[2], hi[3]);
                STS128(ad + 16384, lo[0], lo[1], lo[2], lo[3]);
            }
        }
        __syncthreads();

        // ---- load A fragments for GEMM1 ----
        uint32_t Ah[2][4][4], Al[2][4][4];
        {
            const uint32_t rlo = (uint32_t)(lane & 15);
            const uint32_t khalf = (uint32_t)(lane & 16);
#pragma unroll
            for (int mt = 0; mt < 2; mt++)
#pragma unroll
                for (int kt = 0; kt < 4; kt++) {
                    uint32_t ad = sb + OB_A + SWZ(rb + mt * 16 + rlo, kt * 32 + khalf);
                    ldsm4(Ah[mt][kt], ad);
                    ldsm4(Al[mt][kt], ad + 16384);
                }
        }
        __syncthreads();   // A-staging reads done before next tile's phase A

        float acc[2][8][4];
#pragma unroll
        for (int mt = 0; mt < 2; mt++)
#pragma unroll
            for (int nt = 0; nt < 8; nt++)
#pragma unroll
                for (int q = 0; q < 4; q++) acc[mt][nt][q] = 0.f;

        // ---- GEMM1 (3-split): m_ij = silu(A @ We1 + be1); fused phi_inf / e / m_i ----
        gemm_split(acc, Ah, Al, sb + OB_W1, lane);
        bias_silu(acc, msc + MF_BE1, lr);
        {
            float e[2][2];
#pragma unroll
            for (int mt = 0; mt < 2; mt++) {
                float d0 = 0.f, d1 = 0.f;
#pragma unroll
                for (int nt = 0; nt < 8; nt++) {
                    float2 wf = *(const float2*)(msc + MF_WINF + nt * 8 + lr * 2);
                    d0 += acc[mt][nt][0] * wf.x + acc[mt][nt][1] * wf.y;
                    d1 += acc[mt][nt][2] * wf.x + acc[mt][nt][3] * wf.y;
                }
                d0 += __shfl_xor_sync(0xffffffffu, d0, 1);
                d0 += __shfl_xor_sync(0xffffffffu, d0, 2);
                d1 += __shfl_xor_sync(0xffffffffu, d1, 1);
                d1 += __shfl_xor_sync(0xffffffffu, d1, 2);
                int j0 = tile * 128 + rb + mt * 16 + lq;
                float e0 = sigmoidf_(d0 + rbinf);
                float e1 = sigmoidf_(d1 + rbinf);
                if (j0 == i) e0 = 0.f;
                if (j0 + 8 == i) e1 = 0.f;
                e[mt][0] = e0;
                e[mt][1] = e1;
            }
#pragma unroll
            for (int mt = 0; mt < 2; mt++)
#pragma unroll
                for (int nt = 0; nt < 8; nt++) {
                    acc_mi[nt][0] += e[mt][0] * acc[mt][nt][0] + e[mt][1] * acc[mt][nt][2];
                    acc_mi[nt][1] += e[mt][0] * acc[mt][nt][1] + e[mt][1] * acc[mt][nt][3];
                }
        }
        pack_frags_hi(acc, Ah);

        // ---- GEMM2 (hi-only): t0 = silu(m_ij @ Wx0 + bx0) ----
#pragma unroll
        for (int mt = 0; mt < 2; mt++)
#pragma unroll
            for (int nt = 0; nt < 8; nt++)
#pragma unroll
                for (int q = 0; q < 4; q++) acc[mt][nt][q] = 0.f;
        gemm_hi(acc, Ah, sb + OB_WX0, lane);
        bias_silu(acc, msc + MF_BX0, lr);
        pack_frags_hi(acc, Ah);

        // ---- GEMM3 (hi-only): t1 = silu(t0 @ Wx1 + bx1); phi_x2 + shift ----
#pragma unroll
        for (int mt = 0; mt < 2; mt++)
#pragma unroll
            for (int nt = 0; nt < 8; nt++)
#pragma unroll
                for (int q = 0; q < 4; q++) acc[mt][nt][q] = 0.f;
        gemm_hi(acc, Ah, sb + OB_WX1, lane);
        bias_silu(acc, msc + MF_BX1, lr);
        {
            float part[4][4];
#pragma unroll
            for (int r = 0; r < 4; r++)
#pragma unroll
                for (int hh = 0; hh < 4; hh++) part[r][hh] = 0.f;
#pragma unroll
            for (int nt = 0; nt < 8; nt++)
#pragma unroll
                for (int qp = 0; qp < 2; qp++) {
                    int c = nt * 8 + lr * 2 + qp;
                    float4 w4 = *(const float4*)(msc + MF_WX2 + c * 4);
#pragma unroll
                    for (int mt = 0; mt < 2; mt++) {
                        float v0 = acc[mt][nt][qp];
                        float v1 = acc[mt][nt][2 + qp];
                        part[2 * mt][0] += v0 * w4.x;  part[2 * mt][1] += v0 * w4.y;
                        part[2 * mt][2] += v0 * w4.z;  part[2 * mt][3] += v0 * w4.w;
                        part[2 * mt + 1][0] += v1 * w4.x;  part[2 * mt + 1][1] += v1 * w4.y;
                        part[2 * mt + 1][2] += v1 * w4.z;  part[2 * mt + 1][3] += v1 * w4.w;
                    }
                }
#pragma unroll
            for (int r = 0; r < 4; r++)
#pragma unroll
                for (int hh = 0; hh < 4; hh++) {
                    part[r][hh] += __shfl_xor_sync(0xffffffffu, part[r][hh], 1);
                    part[r][hh] += __shfl_xor_sync(0xffffffffu, part[r][hh], 2);
                }
            const float bxh = msc[MF_BX2 + lr];
            const float xih0 = xi[lr * 3 + 0], xih1 = xi[lr * 3 + 1], xih2 = xi[lr * 3 + 2];
#pragma unroll
            for (int mt = 0; mt < 2; mt++)
#pragma unroll
                for (int half = 0; half < 2; half++) {
                    int row = rb + mt * 16 + lq + half * 8;
                    int j = tile * 128 + row;
                    float d = part[2 * mt + half][lr] + bxh;
                    const float* xa = x + j * 12 + lr * 3;
                    float dx = __ldg(xa + 0) - xih0;
                    float dy = __ldg(xa + 1) - xih1;
                    float dz = __ldg(xa + 2) - xih2;
                    float sqn = dx * dx + dy * dy + dz * dz;
                    float sp = (sqn == 0.f) ? 1.f : sqn;
                    float nrm = sp * rsqf_(sp) + 1.f;   // sqrt(sp)+1
                    float cc = d * rcpf_(nrm);
                    if (j == i) cc = 0.f;
                    sh0 += cc * dx;
                    sh1 += cc * dy;
                    sh2 += cc * dz;
                }
        }
    }

    // ---- reductions (reuse A staging smem) ----
    float* st = (float*)(smem + OB_A);
    __syncthreads();
#pragma unroll
    for (int nt = 0; nt < 8; nt++) {
        st[tid * 16 + nt * 2 + 0] = acc_mi[nt][0];
        st[tid * 16 + nt * 2 + 1] = acc_mi[nt][1];
    }
    __syncthreads();
    if (tid < 64) {
        int nt = tid >> 3, l4 = (tid & 7) >> 1, q = tid & 1;
        float s = 0.f;
#pragma unroll 8
        for (int g = 0; g < 32; g++) s += st[(g * 4 + l4) * 16 + nt * 2 + q];
        g_mi[i * 64 + tid] = s * (1.0f / sqrtf(767.0f));
    }
    __syncthreads();
    st[tid * 3 + 0] = sh0;
    st[tid * 3 + 1] = sh1;
    st[tid * 3 + 2] = sh2;
    __syncthreads();
    if (tid < 12) {
        int hh = tid / 3, d = tid - hh * 3;
        float s = 0.f;
#pragma unroll 8
        for (int g = 0; g < 32; g++) s += st[(g * 4 + hh) * 3 + d];
        out[i * 12 + tid] = xi[tid] + s * (1.0f / 767.0f);
    }
}

// ---------------- phi_h per node ----------------
__global__ void phi_h_kernel(const float* __restrict__ h,
                             const float* __restrict__ w0, const float* __restrict__ b0,
                             const float* __restrict__ w1, const float* __restrict__ b1,
                             const float* __restrict__ w2, const float* __restrict__ b2,
                             float* __restrict__ out) {
    __shared__ float in1[128], t0[64], t1[64];
    const int i = blockIdx.x;
    const int o = threadIdx.x;  // 64
    in1[o] = g_mi[i * 64 + o];
    in1[64 + o] = h[i * 64 + o];
    __syncthreads();
    float a = b0[o];
#pragma unroll 4
    for (int k = 0; k < 128; k++) a += in1[k] * w0[k * 64 + o];
    t0[o] = siluf_(a);
    __syncthreads();
    a = b1[o];
#pragma unroll 4
    for (int k = 0; k < 64; k++) a += t0[k] * w1[k * 64 + o];
    t1[o] = siluf_(a);
    __syncthreads();
    a = b2[o];
#pragma unroll 4
    for (int k = 0; k < 64; k++) a += t1[k] * w2[k * 64 + o];
    out[NN * 12 + i * 64 + o] = h[i * 64 + o] + a;
}

extern "C" void kernel_launch(void* const* d_in, const int* in_sizes, int n_in,
                              void* d_out, int out_size) {
    const float* x    = (const float*)d_in[0];
    const float* h    = (const float*)d_in[1];
    const float* we0  = (const float*)d_in[2];
    const float* be0  = (const float*)d_in[3];
    const float* we1  = (const float*)d_in[4];
    const float* be1  = (const float*)d_in[5];
    const float* winf = (const float*)d_in[6];
    const float* binf = (const float*)d_in[7];
    const float* wx0  = (const float*)d_in[8];
    const float* bx0  = (const float*)d_in[9];
    const float* wx1  = (const float*)d_in[10];
    const float* bx1  = (const float*)d_in[11];
    const float* wx2  = (const float*)d_in[12];
    const float* bx2  = (const float*)d_in[13];
    const float* wh0  = (const float*)d_in[14];
    const float* bh0  = (const float*)d_in[15];
    const float* wh1  = (const float*)d_in[16];
    const float* bh1  = (const float*)d_in[17];
    const float* wh2  = (const float*)d_in[18];
    const float* bh2  = (const float*)d_in[19];
    float* out = (float*)d_out;

    cudaFuncSetAttribute(egcl_main, cudaFuncAttributeMaxDynamicSharedMemorySize, SMEM_BYTES);

    prep_kernel<<<NN, 128>>>(x, h, we0, be0);
    egcl_main<<<NN, 128, SMEM_BYTES>>>(x, we0, we1, be1, winf, binf,
                                       wx0, bx0, wx1, bx1, wx2, bx2, out);
    phi_h_kernel<<<NN, 64>>>(h, wh0, bh0, wh1, bh1, wh2, bh2, out);
}